// round 10
// baseline (speedup 1.0000x reference)
#include <cuda_runtime.h>
#include <cuda_fp16.h>
#include <cstdint>

#define NN 100000
#define EE 1600000
#define FD 128
#define GG 512
#define LL 3
#define TG 64
#define NB ((NN + 1023) / 1024)   /* 98 scan blocks */
#define MTILES ((NN + 127) / 128) /* 782 */

#define PH 136                     /* halves per SMEM row; conflict-free for LDSM too */
#define PHB (PH * 2)               /* 272 bytes per row */
#define TILE_B (128 * PHB)         /* 34816 B per operand tile */
#define GEMM_SMEM (2 * TILE_B)     /* 69632 B */
#define TPIT 132                   /* fp32 pitch for proj T tile */
#define PROJ_SMEM (GEMM_SMEM + 512)

// ---------------- device scratch (no allocs allowed) ----------------
__device__ float  g_h[(size_t)NN * FD];       // fp32 conv2 output (gnorm input)
__device__ __half g_h16[(size_t)NN * FD];     // fp16 activations (gather/proj source)
__device__ __half g_aggr16[(size_t)NN * FD];
__device__ __half g_t16[(size_t)NN * FD];
__device__ __half g_wt16[9 * FD * FD];        // pre-transposed weights [n][k], fp16
__device__ float  g_pool[LL * GG * FD];
__device__ int    g_deg[NN];
__device__ int    g_rowptr[NN + 1];
__device__ int    g_cursor[NN];
__device__ int    g_bsum[NB];
__device__ int    g_boff[NB];
__device__ int    g_srcsorted[EE];
__device__ int    g_gstart[GG + 1];

__device__ __forceinline__ uint32_t smem_u32(const void* p) {
    uint32_t a;
    asm("{ .reg .u64 t; cvta.to.shared.u64 t, %1; cvt.u32.u64 %0, t; }" : "=r"(a) : "l"(p));
    return a;
}
__device__ __forceinline__ void cp16(uint32_t dst, const void* src) {
    asm volatile("cp.async.cg.shared.global [%0], [%1], 16;"
                 :: "r"(dst), "l"(src) : "memory");
}
__device__ __forceinline__ void mma_f16(float* c, const uint32_t* a, const uint32_t* b) {
    asm volatile(
        "mma.sync.aligned.m16n8k16.row.col.f32.f16.f16.f32 "
        "{%0,%1,%2,%3}, {%4,%5,%6,%7}, {%8,%9}, {%0,%1,%2,%3};"
        : "+f"(c[0]), "+f"(c[1]), "+f"(c[2]), "+f"(c[3])
        : "r"(a[0]), "r"(a[1]), "r"(a[2]), "r"(a[3]), "r"(b[0]), "r"(b[1]));
}
__device__ __forceinline__ void ldsm4(uint32_t* r, uint32_t addr) {
    asm volatile("ldmatrix.sync.aligned.m8n8.x4.shared.b16 {%0,%1,%2,%3}, [%4];"
                 : "=r"(r[0]), "=r"(r[1]), "=r"(r[2]), "=r"(r[3]) : "r"(addr));
}
__device__ __forceinline__ void acc_h4(float4& acc, uint2 v) {
    float2 f0 = __half22float2(*(const __half2*)&v.x);
    float2 f1 = __half22float2(*(const __half2*)&v.y);
    acc.x += f0.x; acc.y += f0.y; acc.z += f1.x; acc.w += f1.y;
}

// ---------------- init / CSR build ----------------
__global__ void k_init_zero() {
    int i = blockIdx.x * 256 + threadIdx.x;
    if (i < NN) g_deg[i] = 0;
    if (i < LL * GG * FD) g_pool[i] = 0.f;
}
__global__ void k_hist(const int* __restrict__ dst) {
    int e = blockIdx.x * 256 + threadIdx.x;
    if (e < EE) atomicAdd(&g_deg[dst[e]], 1);
}
__global__ void k_scan1() {
    __shared__ int sh[1024];
    int i = blockIdx.x * 1024 + threadIdx.x;
    int v = (i < NN) ? g_deg[i] : 0;
    sh[threadIdx.x] = v;
    __syncthreads();
    for (int off = 1; off < 1024; off <<= 1) {
        int t = sh[threadIdx.x];
        int a = (threadIdx.x >= off) ? sh[threadIdx.x - off] : 0;
        __syncthreads();
        sh[threadIdx.x] = t + a;
        __syncthreads();
    }
    if (i < NN) g_rowptr[i + 1] = sh[threadIdx.x];
    if (threadIdx.x == 1023) g_bsum[blockIdx.x] = sh[1023];
}
__global__ void k_scan2() {
    __shared__ int sh[128];
    int t = threadIdx.x;
    int v = (t < NB) ? g_bsum[t] : 0;
    sh[t] = v;
    __syncthreads();
    for (int off = 1; off < 128; off <<= 1) {
        int x = sh[t];
        int a = (t >= off) ? sh[t - off] : 0;
        __syncthreads();
        sh[t] = x + a;
        __syncthreads();
    }
    if (t < NB) g_boff[t] = sh[t] - v;
}
__global__ void k_scan3() {
    int i = blockIdx.x * 1024 + threadIdx.x;
    if (i < NN) g_rowptr[i + 1] += g_boff[blockIdx.x];
    if (i == 0) g_rowptr[0] = 0;
}
__global__ void k_copycur() {
    int i = blockIdx.x * 256 + threadIdx.x;
    if (i < NN) g_cursor[i] = g_rowptr[i];
}
__global__ void k_bucket(const int* __restrict__ src, const int* __restrict__ dst) {
    int e = blockIdx.x * 256 + threadIdx.x;
    if (e < EE) {
        int d = dst[e];
        int pos = atomicAdd(&g_cursor[d], 1);
        g_srcsorted[pos] = src[e];
    }
}
__global__ void k_gstart(const int* __restrict__ batch) {
    int g = blockIdx.x * 256 + threadIdx.x;
    if (g <= GG) {
        int lo = 0, hi = NN;
        while (lo < hi) {
            int mid = (lo + hi) >> 1;
            if (batch[mid] < g) lo = mid + 1; else hi = mid;
        }
        g_gstart[g] = lo;
    }
}

// ---------------- x -> fp16 ----------------
__global__ void k_x16(const float* __restrict__ x) {
    int i = blockIdx.x * 256 + threadIdx.x;
    if (i < NN * FD / 2) {
        float2 v = ((const float2*)x)[i];
        ((__half2*)g_h16)[i] = __floats2half2_rn(v.x, v.y);
    }
}

// ---------------- weight transpose -> fp16 [n][k] ----------------
__global__ void k_wtrans(const float* __restrict__ w1, const float* __restrict__ w2,
                         const float* __restrict__ w3) {
    __shared__ float t[32][33];
    int mi = blockIdx.z;
    const float* src = (mi < 3) ? (w1 + (size_t)mi * FD * FD)
                     : (mi < 6) ? (w2 + (size_t)(mi - 3) * FD * FD)
                                : (w3 + (size_t)(mi - 6) * FD * FD);
    __half* dst = g_wt16 + (size_t)mi * FD * FD;
    int x0 = blockIdx.x * 32, y0 = blockIdx.y * 32;
    for (int dy = threadIdx.y; dy < 32; dy += 8)
        t[dy][threadIdx.x] = src[(size_t)(y0 + dy) * FD + x0 + threadIdx.x];
    __syncthreads();
    for (int dy = threadIdx.y; dy < 32; dy += 8)
        dst[(size_t)(x0 + dy) * FD + y0 + threadIdx.x] = __float2half(t[threadIdx.x][dy]);
}

// ---------------- aggregation + GIN combine (fp16 in, fp16 out) ----------------
__global__ void __launch_bounds__(256) k_aggr16(const float* __restrict__ epsp) {
    int node = blockIdx.x * 8 + (threadIdx.x >> 5);
    if (node >= NN) return;
    int lane = threadIdx.x & 31;
    int s = g_rowptr[node], e = g_rowptr[node + 1];
    float alpha = 1.0f + epsp[0];
    const uint2* hp = (const uint2*)g_h16;
    uint2 hv = hp[(size_t)node * 32 + lane];
    float2 f0 = __half22float2(*(const __half2*)&hv.x);
    float2 f1 = __half22float2(*(const __half2*)&hv.y);
    float4 acc = make_float4(alpha * f0.x, alpha * f0.y, alpha * f1.x, alpha * f1.y);
    int j = s;
    for (; j + 3 < e; j += 4) {
        int s0 = g_srcsorted[j],     s1 = g_srcsorted[j + 1];
        int s2 = g_srcsorted[j + 2], s3 = g_srcsorted[j + 3];
        uint2 v0 = hp[(size_t)s0 * 32 + lane];
        uint2 v1 = hp[(size_t)s1 * 32 + lane];
        uint2 v2 = hp[(size_t)s2 * 32 + lane];
        uint2 v3 = hp[(size_t)s3 * 32 + lane];
        acc_h4(acc, v0); acc_h4(acc, v1); acc_h4(acc, v2); acc_h4(acc, v3);
    }
    for (; j < e; j++) acc_h4(acc, hp[(size_t)g_srcsorted[j] * 32 + lane]);
    uint2 o;
    *(__half2*)&o.x = __floats2half2_rn(acc.x, acc.y);
    *(__half2*)&o.y = __floats2half2_rn(acc.z, acc.w);
    ((uint2*)g_aggr16)[(size_t)node * 32 + lane] = o;
}

// ---------------- fp16 mma GEMM, single-stage full-K tiles, LDSM frags ----------------
// out16 != 0: C16 = fp16(relu(acc+bias)).  out16 == 0: C32 = acc+bias (fp32).
__global__ void __launch_bounds__(256) k_gemm16(
    const __half* __restrict__ A16, const __half* __restrict__ Wt16,
    const float* __restrict__ bias,
    __half* __restrict__ C16, float* __restrict__ C32, int M, int out16)
{
    extern __shared__ __half smem[];
    uint32_t sb = smem_u32(smem);
    int tid = threadIdx.x;
    int w = tid >> 5, lane = tid & 31;
    int m0 = blockIdx.x * 128;

    // stage A (side 0) + B (side 1): 4096 x 16B
#pragma unroll
    for (int i = 0; i < 16; i++) {
        int o = i * 256 + tid;
        int side = o >> 11;
        int idx = o & 2047;
        int row = idx >> 4;
        int q = idx & 15;
        uint32_t dst = sb + (uint32_t)(side * TILE_B + row * PHB + q * 16);
        if (side == 0) {
            int m = m0 + row;
            cp16(dst, A16 + ((m < M) ? ((size_t)m * FD + q * 8) : (size_t)(q * 8)));
        } else {
            cp16(dst, Wt16 + (size_t)row * FD + q * 8);
        }
    }
    asm volatile("cp.async.commit_group;" ::: "memory");
    asm volatile("cp.async.wait_group 0;" ::: "memory");
    __syncthreads();

    int warpM = w >> 2, warpN = w & 3;
    int g = lane >> 2, t = lane & 3;
    int sub = lane >> 3, j8 = lane & 7;

    // LDSM base addresses (per lane)
    // A x4 (per ma): M0=(rows lo, k lo) M1=(rows hi, k lo) M2=(rows lo, k hi) M3=(rows hi, k hi)
    uint32_t aBase = sb + (uint32_t)((warpM * 64 + j8 + (sub & 1) * 8) * PHB + (sub >> 1) * 16);
    // B x4 (per nb-pair): M0=(nb_lo, k lo) M1=(nb_lo, k hi) M2=(nb_hi, k lo) M3=(nb_hi, k hi)
    uint32_t bBase = sb + (uint32_t)(TILE_B + (warpN * 32 + j8 + (sub >> 1) * 8) * PHB + (sub & 1) * 16);

    float c[4][4][4];
#pragma unroll
    for (int ma = 0; ma < 4; ma++)
#pragma unroll
        for (int nb = 0; nb < 4; nb++)
#pragma unroll
            for (int r = 0; r < 4; r++) c[ma][nb][r] = 0.f;

#pragma unroll
    for (int ks = 0; ks < 8; ks++) {
        uint32_t kofs = ks * 32;              // 16 halves = 32 B
        uint32_t af[4][4];
#pragma unroll
        for (int ma = 0; ma < 4; ma++)
            ldsm4(af[ma], aBase + ma * 16 * PHB + kofs);
        uint32_t bf01[4], bf23[4];
        ldsm4(bf01, bBase + kofs);            // nb0, nb1
        ldsm4(bf23, bBase + 16 * PHB + kofs); // nb2, nb3
#pragma unroll
        for (int ma = 0; ma < 4; ma++) {
            mma_f16(c[ma][0], af[ma], &bf01[0]);
            mma_f16(c[ma][1], af[ma], &bf01[2]);
            mma_f16(c[ma][2], af[ma], &bf23[0]);
            mma_f16(c[ma][3], af[ma], &bf23[2]);
        }
    }

#pragma unroll
    for (int ma = 0; ma < 4; ma++) {
        int r0 = m0 + warpM * 64 + ma * 16 + g;
#pragma unroll
        for (int nb = 0; nb < 4; nb++) {
            int cn = warpN * 32 + nb * 8 + 2 * t;
            float b0 = bias[cn], b1 = bias[cn + 1];
            float o0 = c[ma][nb][0] + b0, o1 = c[ma][nb][1] + b1;
            float o2 = c[ma][nb][2] + b0, o3 = c[ma][nb][3] + b1;
            if (out16) {
                uint32_t p0, p1;
                *(__half2*)&p0 = __floats2half2_rn(fmaxf(o0, 0.f), fmaxf(o1, 0.f));
                *(__half2*)&p1 = __floats2half2_rn(fmaxf(o2, 0.f), fmaxf(o3, 0.f));
                if (r0 < M)     ((uint32_t*)C16)[(size_t)r0 * 64 + (cn >> 1)]       = p0;
                if (r0 + 8 < M) ((uint32_t*)C16)[(size_t)(r0 + 8) * 64 + (cn >> 1)] = p1;
            } else {
                if (r0 < M)     *(float2*)&C32[(size_t)r0 * FD + cn]       = make_float2(o0, o1);
                if (r0 + 8 < M) *(float2*)&C32[(size_t)(r0 + 8) * FD + cn] = make_float2(o2, o3);
            }
        }
    }
}

// ---------------- proj GEMM (fp16, LDSM) fused with pool partial-sums ----------------
__global__ void __launch_bounds__(256) k_gemm_proj16(
    const __half* __restrict__ A16, const __half* __restrict__ Wt16,
    const float* __restrict__ bias,
    const int* __restrict__ batch, float* __restrict__ poolp, int M)
{
    extern __shared__ __half smem[];
    uint32_t sb = smem_u32(smem);
    float* Tt = (float*)smem;                         // T tile overwrites operands
    int* sbatch = (int*)((char*)smem + GEMM_SMEM);
    int tid = threadIdx.x;
    int w = tid >> 5, lane = tid & 31;
    int m0 = blockIdx.x * 128;

#pragma unroll
    for (int i = 0; i < 16; i++) {
        int o = i * 256 + tid;
        int side = o >> 11;
        int idx = o & 2047;
        int row = idx >> 4;
        int q = idx & 15;
        uint32_t dst = sb + (uint32_t)(side * TILE_B + row * PHB + q * 16);
        if (side == 0) {
            int m = m0 + row;
            cp16(dst, A16 + ((m < M) ? ((size_t)m * FD + q * 8) : (size_t)(q * 8)));
        } else {
            cp16(dst, Wt16 + (size_t)row * FD + q * 8);
        }
    }
    asm volatile("cp.async.commit_group;" ::: "memory");
    asm volatile("cp.async.wait_group 0;" ::: "memory");
    __syncthreads();

    int warpM = w >> 2, warpN = w & 3;
    int g = lane >> 2, t = lane & 3;
    int sub = lane >> 3, j8 = lane & 7;

    uint32_t aBase = sb + (uint32_t)((warpM * 64 + j8 + (sub & 1) * 8) * PHB + (sub >> 1) * 16);
    uint32_t bBase = sb + (uint32_t)(TILE_B + (warpN * 32 + j8 + (sub >> 1) * 8) * PHB + (sub & 1) * 16);

    float c[4][4][4];
#pragma unroll
    for (int ma = 0; ma < 4; ma++)
#pragma unroll
        for (int nb = 0; nb < 4; nb++)
#pragma unroll
            for (int r = 0; r < 4; r++) c[ma][nb][r] = 0.f;

#pragma unroll
    for (int ks = 0; ks < 8; ks++) {
        uint32_t kofs = ks * 32;
        uint32_t af[4][4];
#pragma unroll
        for (int ma = 0; ma < 4; ma++)
            ldsm4(af[ma], aBase + ma * 16 * PHB + kofs);
        uint32_t bf01[4], bf23[4];
        ldsm4(bf01, bBase + kofs);
        ldsm4(bf23, bBase + 16 * PHB + kofs);
#pragma unroll
        for (int ma = 0; ma < 4; ma++) {
            mma_f16(c[ma][0], af[ma], &bf01[0]);
            mma_f16(c[ma][1], af[ma], &bf01[2]);
            mma_f16(c[ma][2], af[ma], &bf23[0]);
            mma_f16(c[ma][3], af[ma], &bf23[2]);
        }
    }
    __syncthreads();   // operands dead; reuse SMEM for T tile

    if (tid < 128) sbatch[tid] = (m0 + tid < M) ? batch[m0 + tid] : -1;
#pragma unroll
    for (int ma = 0; ma < 4; ma++) {
        int r0 = warpM * 64 + ma * 16 + g;
#pragma unroll
        for (int nb = 0; nb < 4; nb++) {
            int cn = warpN * 32 + nb * 8 + 2 * t;
            float b0 = bias[cn], b1v = bias[cn + 1];
            Tt[r0 * TPIT + cn]           = fmaxf(c[ma][nb][0] + b0, 0.f);
            Tt[r0 * TPIT + cn + 1]       = fmaxf(c[ma][nb][1] + b1v, 0.f);
            Tt[(r0 + 8) * TPIT + cn]     = fmaxf(c[ma][nb][2] + b0, 0.f);
            Tt[(r0 + 8) * TPIT + cn + 1] = fmaxf(c[ma][nb][3] + b1v, 0.f);
        }
    }
    __syncthreads();

    // segmented column sums over sorted batch ids
    {
        int f = tid & 127;
        int half = tid >> 7;
        int base = half * 64;
        if (m0 + base < M) {
            float acc = 0.f;
            int curg = sbatch[base];
            for (int i = 0; i < 64; i++) {
                int gi = sbatch[base + i];
                if (gi < 0) break;
                if (gi != curg) {
                    atomicAdd(&poolp[(size_t)curg * FD + f], acc);
                    acc = 0.f;
                    curg = gi;
                }
                acc += Tt[(base + i) * TPIT + f];
            }
            if (curg >= 0) atomicAdd(&poolp[(size_t)curg * FD + f], acc);
        }
    }
}

// ---------------- GraphNorm (+relu): fp32 in, fp16 out ----------------
__global__ void __launch_bounds__(128) k_gnorm(
    const float* __restrict__ h,
    const float* __restrict__ scale, const float* __restrict__ weight,
    const float* __restrict__ bias)
{
    int g = blockIdx.x;
    int f = threadIdx.x;
    int s = g_gstart[g], e = g_gstart[g + 1];
    float cnt = fmaxf((float)(e - s), 1.0f);

    float sum = 0.f, sq = 0.f;
#pragma unroll 4
    for (int i = s; i < e; i++) {
        float v = h[(size_t)i * FD + f];
        sum += v;
        sq += v * v;
    }
    float mean = sum / cnt;
    float ms = mean * scale[f];
    float var = sq / cnt - 2.f * ms * mean + ms * ms;
    float inv = weight[f] * rsqrtf(var + 1e-8f);
    float bf = bias[f];

#pragma unroll 4
    for (int i = s; i < e; i++) {
        float o = fmaxf(inv * (h[(size_t)i * FD + f] - ms) + bf, 0.f);
        g_h16[(size_t)i * FD + f] = __float2half(o);
    }
}

// ---------------- final tiny GEMM: out[g, lofs+f] = pool[g]@W2 + cnt*b2 ----------------
__global__ void __launch_bounds__(128) k_pool2(
    const float* __restrict__ poolp,
    const float* __restrict__ w2, const float* __restrict__ b2,
    float* __restrict__ out, int lofs)
{
    __shared__ float sp[128];
    int g = blockIdx.x;
    int f = threadIdx.x;
    sp[f] = poolp[(size_t)g * FD + f];
    __syncthreads();
    if (f < TG) {
        int cnt = g_gstart[g + 1] - g_gstart[g];
        float o = (float)cnt * b2[f];
#pragma unroll 8
        for (int k = 0; k < FD; k++) o += sp[k] * w2[k * TG + f];
        out[(size_t)g * (LL * TG) + lofs + f] = o;
    }
}

// ---------------- launcher ----------------
extern "C" void kernel_launch(void* const* d_in, const int* in_sizes, int n_in,
                              void* d_out, int out_size) {
    const float* x        = (const float*)d_in[0];
    const int*   edge     = (const int*)d_in[1];
    const int*   batch    = (const int*)d_in[2];
    const float* conv_w1  = (const float*)d_in[3];
    const float* conv_b1  = (const float*)d_in[4];
    const float* conv_w2  = (const float*)d_in[5];
    const float* conv_b2  = (const float*)d_in[6];
    const float* eps      = (const float*)d_in[7];
    const float* gn_scale = (const float*)d_in[8];
    const float* gn_weight= (const float*)d_in[9];
    const float* gn_bias  = (const float*)d_in[10];
    const float* proj_w1  = (const float*)d_in[11];
    const float* proj_b1  = (const float*)d_in[12];
    const float* proj_w2  = (const float*)d_in[13];
    const float* proj_b2  = (const float*)d_in[14];
    float* out = (float*)d_out;

    const int* src = edge;
    const int* dst = edge + EE;

    float *p_h, *p_pool;
    __half *p_h16, *p_a16, *p_t16, *p_wt16;
    cudaGetSymbolAddress((void**)&p_h, g_h);
    cudaGetSymbolAddress((void**)&p_pool, g_pool);
    cudaGetSymbolAddress((void**)&p_h16, g_h16);
    cudaGetSymbolAddress((void**)&p_a16, g_aggr16);
    cudaGetSymbolAddress((void**)&p_t16, g_t16);
    cudaGetSymbolAddress((void**)&p_wt16, g_wt16);

    cudaFuncSetAttribute(k_gemm16, cudaFuncAttributeMaxDynamicSharedMemorySize, GEMM_SMEM);
    cudaFuncSetAttribute(k_gemm_proj16, cudaFuncAttributeMaxDynamicSharedMemorySize, PROJ_SMEM);

    // init + CSR build + graph starts + weight transpose + x->fp16
    k_init_zero<<<(LL * GG * FD + 255) / 256, 256>>>();
    k_hist<<<(EE + 255) / 256, 256>>>(dst);
    k_scan1<<<NB, 1024>>>();
    k_scan2<<<1, 128>>>();
    k_scan3<<<NB, 1024>>>();
    k_copycur<<<(NN + 255) / 256, 256>>>();
    k_bucket<<<(EE + 255) / 256, 256>>>(src, dst);
    k_gstart<<<3, 256>>>(batch);
    k_wtrans<<<dim3(4, 4, 9), dim3(32, 8)>>>(conv_w1, conv_w2, proj_w1);
    k_x16<<<(NN * FD / 2 + 255) / 256, 256>>>(x);

    for (int l = 0; l < LL; l++) {
        // aggr16 = fp16((1+eps)h + sum_j h_j)
        k_aggr16<<<(NN + 7) / 8, 256>>>(eps + l);
        // t16 = fp16(relu(aggr16 @ W1 + b1))
        k_gemm16<<<MTILES, 256, GEMM_SMEM>>>(p_a16,
                                             p_wt16 + (size_t)l * FD * FD,
                                             conv_b1 + (size_t)l * FD,
                                             p_t16, nullptr, NN, 1);
        // h = t16 @ W2 + b2 (fp32)
        k_gemm16<<<MTILES, 256, GEMM_SMEM>>>(p_t16,
                                             p_wt16 + (size_t)(3 + l) * FD * FD,
                                             conv_b2 + (size_t)l * FD,
                                             nullptr, p_h, NN, 0);
        // GraphNorm + relu -> h16
        k_gnorm<<<GG, 128>>>(p_h, gn_scale + (size_t)l * FD,
                             gn_weight + (size_t)l * FD, gn_bias + (size_t)l * FD);
        // pool_l += segsum(relu(h16 @ W1p + b1p))
        k_gemm_proj16<<<MTILES, 256, PROJ_SMEM>>>(p_h16,
                                                  p_wt16 + (size_t)(6 + l) * FD * FD,
                                                  proj_b1 + (size_t)l * FD,
                                                  batch, p_pool + (size_t)l * GG * FD, NN);
        // out_l = pool_l @ W2p + cnt*b2p
        k_pool2<<<GG, 128>>>(p_pool + (size_t)l * GG * FD,
                             proj_w2 + (size_t)l * FD * TG,
                             proj_b2 + (size_t)l * TG, out, l * TG);
    }
}

// round 11
// speedup vs baseline: 1.0842x; 1.0842x over previous
#include <cuda_runtime.h>
#include <cuda_fp16.h>
#include <cstdint>

#define NN 100000
#define EE 1600000
#define FD 128
#define GG 512
#define LL 3
#define TG 64
#define NB ((NN + 1023) / 1024)   /* 98 scan blocks */
#define MTILES ((NN + 127) / 128) /* 782 */

#define PH 136                     /* halves per SMEM row; conflict-free for LDSM too */
#define PHB (PH * 2)               /* 272 bytes per row */
#define TILE_B (128 * PHB)         /* 34816 B per operand tile */
#define GEMM_SMEM (2 * TILE_B)     /* 69632 B */
#define TPIT 132                   /* fp32 pitch for proj T tile */
#define PROJ_SMEM (GEMM_SMEM + 512)

// ---------------- device scratch (no allocs allowed) ----------------
__device__ float  g_h[(size_t)NN * FD];       // fp32 conv2 output (gnorm input)
__device__ __half g_h16[(size_t)NN * FD];     // fp16 activations (gather/proj source)
__device__ __half g_aggr16[(size_t)NN * FD];
__device__ __half g_t16[(size_t)NN * FD];
__device__ __half g_wt16[9 * FD * FD];        // pre-transposed weights [n][k], fp16
__device__ float  g_pool[LL * GG * FD];
__device__ int    g_deg[NN];
__device__ int    g_rowptr[NN + 1];
__device__ int    g_cursor[NN];
__device__ int    g_bsum[NB];
__device__ int    g_boff[NB];
__device__ int    g_srcsorted[EE];
__device__ int    g_gstart[GG + 1];

__device__ __forceinline__ uint32_t smem_u32(const void* p) {
    uint32_t a;
    asm("{ .reg .u64 t; cvta.to.shared.u64 t, %1; cvt.u32.u64 %0, t; }" : "=r"(a) : "l"(p));
    return a;
}
__device__ __forceinline__ void cp16(uint32_t dst, const void* src) {
    asm volatile("cp.async.cg.shared.global [%0], [%1], 16;"
                 :: "r"(dst), "l"(src) : "memory");
}
__device__ __forceinline__ void mma_f16(float* c, const uint32_t* a, const uint32_t* b) {
    asm volatile(
        "mma.sync.aligned.m16n8k16.row.col.f32.f16.f16.f32 "
        "{%0,%1,%2,%3}, {%4,%5,%6,%7}, {%8,%9}, {%0,%1,%2,%3};"
        : "+f"(c[0]), "+f"(c[1]), "+f"(c[2]), "+f"(c[3])
        : "r"(a[0]), "r"(a[1]), "r"(a[2]), "r"(a[3]), "r"(b[0]), "r"(b[1]));
}
__device__ __forceinline__ void ldsm4(uint32_t* r, uint32_t addr) {
    asm volatile("ldmatrix.sync.aligned.m8n8.x4.shared.b16 {%0,%1,%2,%3}, [%4];"
                 : "=r"(r[0]), "=r"(r[1]), "=r"(r[2]), "=r"(r[3]) : "r"(addr));
}
__device__ __forceinline__ void acc_h4(float4& acc, uint2 v) {
    float2 f0 = __half22float2(*(const __half2*)&v.x);
    float2 f1 = __half22float2(*(const __half2*)&v.y);
    acc.x += f0.x; acc.y += f0.y; acc.z += f1.x; acc.w += f1.y;
}

// ---------------- init / CSR build ----------------
__global__ void k_init_zero() {
    int i = blockIdx.x * 256 + threadIdx.x;
    if (i < NN) g_deg[i] = 0;
    if (i < LL * GG * FD) g_pool[i] = 0.f;
}
__global__ void k_hist(const int* __restrict__ dst) {
    int e = blockIdx.x * 256 + threadIdx.x;
    if (e < EE) atomicAdd(&g_deg[dst[e]], 1);
}
__global__ void k_scan1() {
    __shared__ int sh[1024];
    int i = blockIdx.x * 1024 + threadIdx.x;
    int v = (i < NN) ? g_deg[i] : 0;
    sh[threadIdx.x] = v;
    __syncthreads();
    for (int off = 1; off < 1024; off <<= 1) {
        int t = sh[threadIdx.x];
        int a = (threadIdx.x >= off) ? sh[threadIdx.x - off] : 0;
        __syncthreads();
        sh[threadIdx.x] = t + a;
        __syncthreads();
    }
    if (i < NN) g_rowptr[i + 1] = sh[threadIdx.x];
    if (threadIdx.x == 1023) g_bsum[blockIdx.x] = sh[1023];
}
__global__ void k_scan2() {
    __shared__ int sh[128];
    int t = threadIdx.x;
    int v = (t < NB) ? g_bsum[t] : 0;
    sh[t] = v;
    __syncthreads();
    for (int off = 1; off < 128; off <<= 1) {
        int x = sh[t];
        int a = (t >= off) ? sh[t - off] : 0;
        __syncthreads();
        sh[t] = x + a;
        __syncthreads();
    }
    if (t < NB) g_boff[t] = sh[t] - v;
}
__global__ void k_scan3() {
    int i = blockIdx.x * 1024 + threadIdx.x;
    if (i < NN) g_rowptr[i + 1] += g_boff[blockIdx.x];
    if (i == 0) g_rowptr[0] = 0;
}
__global__ void k_copycur() {
    int i = blockIdx.x * 256 + threadIdx.x;
    if (i < NN) g_cursor[i] = g_rowptr[i];
}
__global__ void k_bucket(const int* __restrict__ src, const int* __restrict__ dst) {
    int e = blockIdx.x * 256 + threadIdx.x;
    if (e < EE) {
        int d = dst[e];
        int pos = atomicAdd(&g_cursor[d], 1);
        g_srcsorted[pos] = src[e];
    }
}
__global__ void k_gstart(const int* __restrict__ batch) {
    int g = blockIdx.x * 256 + threadIdx.x;
    if (g <= GG) {
        int lo = 0, hi = NN;
        while (lo < hi) {
            int mid = (lo + hi) >> 1;
            if (batch[mid] < g) lo = mid + 1; else hi = mid;
        }
        g_gstart[g] = lo;
    }
}

// ---------------- x -> fp16 ----------------
__global__ void k_x16(const float* __restrict__ x) {
    int i = blockIdx.x * 256 + threadIdx.x;
    if (i < NN * FD / 2) {
        float2 v = ((const float2*)x)[i];
        ((__half2*)g_h16)[i] = __floats2half2_rn(v.x, v.y);
    }
}

// ---------------- weight transpose -> fp16 [n][k] ----------------
__global__ void k_wtrans(const float* __restrict__ w1, const float* __restrict__ w2,
                         const float* __restrict__ w3) {
    __shared__ float t[32][33];
    int mi = blockIdx.z;
    const float* src = (mi < 3) ? (w1 + (size_t)mi * FD * FD)
                     : (mi < 6) ? (w2 + (size_t)(mi - 3) * FD * FD)
                                : (w3 + (size_t)(mi - 6) * FD * FD);
    __half* dst = g_wt16 + (size_t)mi * FD * FD;
    int x0 = blockIdx.x * 32, y0 = blockIdx.y * 32;
    for (int dy = threadIdx.y; dy < 32; dy += 8)
        t[dy][threadIdx.x] = src[(size_t)(y0 + dy) * FD + x0 + threadIdx.x];
    __syncthreads();
    for (int dy = threadIdx.y; dy < 32; dy += 8)
        dst[(size_t)(x0 + dy) * FD + y0 + threadIdx.x] = __float2half(t[threadIdx.x][dy]);
}

// ---------------- aggregation + GIN combine (fp16 in, fp16 out) ----------------
__global__ void __launch_bounds__(256) k_aggr16(const float* __restrict__ epsp) {
    int node = blockIdx.x * 8 + (threadIdx.x >> 5);
    if (node >= NN) return;
    int lane = threadIdx.x & 31;
    int s = g_rowptr[node], e = g_rowptr[node + 1];
    float alpha = 1.0f + epsp[0];
    const uint2* hp = (const uint2*)g_h16;
    uint2 hv = hp[(size_t)node * 32 + lane];
    float2 f0 = __half22float2(*(const __half2*)&hv.x);
    float2 f1 = __half22float2(*(const __half2*)&hv.y);
    float4 acc = make_float4(alpha * f0.x, alpha * f0.y, alpha * f1.x, alpha * f1.y);
    int j = s;
    for (; j + 3 < e; j += 4) {
        int s0 = g_srcsorted[j],     s1 = g_srcsorted[j + 1];
        int s2 = g_srcsorted[j + 2], s3 = g_srcsorted[j + 3];
        uint2 v0 = hp[(size_t)s0 * 32 + lane];
        uint2 v1 = hp[(size_t)s1 * 32 + lane];
        uint2 v2 = hp[(size_t)s2 * 32 + lane];
        uint2 v3 = hp[(size_t)s3 * 32 + lane];
        acc_h4(acc, v0); acc_h4(acc, v1); acc_h4(acc, v2); acc_h4(acc, v3);
    }
    for (; j < e; j++) acc_h4(acc, hp[(size_t)g_srcsorted[j] * 32 + lane]);
    uint2 o;
    *(__half2*)&o.x = __floats2half2_rn(acc.x, acc.y);
    *(__half2*)&o.y = __floats2half2_rn(acc.z, acc.w);
    ((uint2*)g_aggr16)[(size_t)node * 32 + lane] = o;
}

// ---------------- fp16 mma GEMM, single-stage full-K tiles, LDSM frags ----------------
// out16 != 0: C16 = fp16(relu(acc+bias)).  out16 == 0: C32 = acc+bias (fp32).
__global__ void __launch_bounds__(256) k_gemm16(
    const __half* __restrict__ A16, const __half* __restrict__ Wt16,
    const float* __restrict__ bias,
    __half* __restrict__ C16, float* __restrict__ C32, int M, int out16)
{
    extern __shared__ __half smem[];
    uint32_t sb = smem_u32(smem);
    int tid = threadIdx.x;
    int w = tid >> 5, lane = tid & 31;
    int m0 = blockIdx.x * 128;

#pragma unroll
    for (int i = 0; i < 16; i++) {
        int o = i * 256 + tid;
        int side = o >> 11;
        int idx = o & 2047;
        int row = idx >> 4;
        int q = idx & 15;
        uint32_t dst = sb + (uint32_t)(side * TILE_B + row * PHB + q * 16);
        if (side == 0) {
            int m = m0 + row;
            cp16(dst, A16 + ((m < M) ? ((size_t)m * FD + q * 8) : (size_t)(q * 8)));
        } else {
            cp16(dst, Wt16 + (size_t)row * FD + q * 8);
        }
    }
    asm volatile("cp.async.commit_group;" ::: "memory");
    asm volatile("cp.async.wait_group 0;" ::: "memory");
    __syncthreads();

    int warpM = w >> 2, warpN = w & 3;
    int g = lane >> 2, t = lane & 3;
    int sub = lane >> 3, j8 = lane & 7;

    uint32_t aBase = sb + (uint32_t)((warpM * 64 + j8 + (sub & 1) * 8) * PHB + (sub >> 1) * 16);
    uint32_t bBase = sb + (uint32_t)(TILE_B + (warpN * 32 + j8 + (sub >> 1) * 8) * PHB + (sub & 1) * 16);

    float c[4][4][4];
#pragma unroll
    for (int ma = 0; ma < 4; ma++)
#pragma unroll
        for (int nb = 0; nb < 4; nb++)
#pragma unroll
            for (int r = 0; r < 4; r++) c[ma][nb][r] = 0.f;

#pragma unroll
    for (int ks = 0; ks < 8; ks++) {
        uint32_t kofs = ks * 32;
        uint32_t af[4][4];
#pragma unroll
        for (int ma = 0; ma < 4; ma++)
            ldsm4(af[ma], aBase + ma * 16 * PHB + kofs);
        uint32_t bf01[4], bf23[4];
        ldsm4(bf01, bBase + kofs);
        ldsm4(bf23, bBase + 16 * PHB + kofs);
#pragma unroll
        for (int ma = 0; ma < 4; ma++) {
            mma_f16(c[ma][0], af[ma], &bf01[0]);
            mma_f16(c[ma][1], af[ma], &bf01[2]);
            mma_f16(c[ma][2], af[ma], &bf23[0]);
            mma_f16(c[ma][3], af[ma], &bf23[2]);
        }
    }

#pragma unroll
    for (int ma = 0; ma < 4; ma++) {
        int r0 = m0 + warpM * 64 + ma * 16 + g;
#pragma unroll
        for (int nb = 0; nb < 4; nb++) {
            int cn = warpN * 32 + nb * 8 + 2 * t;
            float b0 = bias[cn], b1 = bias[cn + 1];
            float o0 = c[ma][nb][0] + b0, o1 = c[ma][nb][1] + b1;
            float o2 = c[ma][nb][2] + b0, o3 = c[ma][nb][3] + b1;
            if (out16) {
                uint32_t p0, p1;
                *(__half2*)&p0 = __floats2half2_rn(fmaxf(o0, 0.f), fmaxf(o1, 0.f));
                *(__half2*)&p1 = __floats2half2_rn(fmaxf(o2, 0.f), fmaxf(o3, 0.f));
                if (r0 < M)     ((uint32_t*)C16)[(size_t)r0 * 64 + (cn >> 1)]       = p0;
                if (r0 + 8 < M) ((uint32_t*)C16)[(size_t)(r0 + 8) * 64 + (cn >> 1)] = p1;
            } else {
                if (r0 < M)     *(float2*)&C32[(size_t)r0 * FD + cn]       = make_float2(o0, o1);
                if (r0 + 8 < M) *(float2*)&C32[(size_t)(r0 + 8) * FD + cn] = make_float2(o2, o3);
            }
        }
    }
}

// ---------------- proj GEMM (fp16, LDSM) fused with pool partial-sums ----------------
__global__ void __launch_bounds__(256) k_gemm_proj16(
    const __half* __restrict__ A16, const __half* __restrict__ Wt16,
    const float* __restrict__ bias,
    const int* __restrict__ batch, float* __restrict__ poolp, int M)
{
    extern __shared__ __half smem[];
    uint32_t sb = smem_u32(smem);
    float* Tt = (float*)smem;
    int* sbatch = (int*)((char*)smem + GEMM_SMEM);
    int tid = threadIdx.x;
    int w = tid >> 5, lane = tid & 31;
    int m0 = blockIdx.x * 128;

#pragma unroll
    for (int i = 0; i < 16; i++) {
        int o = i * 256 + tid;
        int side = o >> 11;
        int idx = o & 2047;
        int row = idx >> 4;
        int q = idx & 15;
        uint32_t dst = sb + (uint32_t)(side * TILE_B + row * PHB + q * 16);
        if (side == 0) {
            int m = m0 + row;
            cp16(dst, A16 + ((m < M) ? ((size_t)m * FD + q * 8) : (size_t)(q * 8)));
        } else {
            cp16(dst, Wt16 + (size_t)row * FD + q * 8);
        }
    }
    asm volatile("cp.async.commit_group;" ::: "memory");
    asm volatile("cp.async.wait_group 0;" ::: "memory");
    __syncthreads();

    int warpM = w >> 2, warpN = w & 3;
    int g = lane >> 2, t = lane & 3;
    int sub = lane >> 3, j8 = lane & 7;

    uint32_t aBase = sb + (uint32_t)((warpM * 64 + j8 + (sub & 1) * 8) * PHB + (sub >> 1) * 16);
    uint32_t bBase = sb + (uint32_t)(TILE_B + (warpN * 32 + j8 + (sub >> 1) * 8) * PHB + (sub & 1) * 16);

    float c[4][4][4];
#pragma unroll
    for (int ma = 0; ma < 4; ma++)
#pragma unroll
        for (int nb = 0; nb < 4; nb++)
#pragma unroll
            for (int r = 0; r < 4; r++) c[ma][nb][r] = 0.f;

#pragma unroll
    for (int ks = 0; ks < 8; ks++) {
        uint32_t kofs = ks * 32;
        uint32_t af[4][4];
#pragma unroll
        for (int ma = 0; ma < 4; ma++)
            ldsm4(af[ma], aBase + ma * 16 * PHB + kofs);
        uint32_t bf01[4], bf23[4];
        ldsm4(bf01, bBase + kofs);
        ldsm4(bf23, bBase + 16 * PHB + kofs);
#pragma unroll
        for (int ma = 0; ma < 4; ma++) {
            mma_f16(c[ma][0], af[ma], &bf01[0]);
            mma_f16(c[ma][1], af[ma], &bf01[2]);
            mma_f16(c[ma][2], af[ma], &bf23[0]);
            mma_f16(c[ma][3], af[ma], &bf23[2]);
        }
    }
    __syncthreads();   // operands dead; reuse SMEM for T tile

    if (tid < 128) sbatch[tid] = (m0 + tid < M) ? batch[m0 + tid] : -1;
#pragma unroll
    for (int ma = 0; ma < 4; ma++) {
        int r0 = warpM * 64 + ma * 16 + g;
#pragma unroll
        for (int nb = 0; nb < 4; nb++) {
            int cn = warpN * 32 + nb * 8 + 2 * t;
            float b0 = bias[cn], b1v = bias[cn + 1];
            Tt[r0 * TPIT + cn]           = fmaxf(c[ma][nb][0] + b0, 0.f);
            Tt[r0 * TPIT + cn + 1]       = fmaxf(c[ma][nb][1] + b1v, 0.f);
            Tt[(r0 + 8) * TPIT + cn]     = fmaxf(c[ma][nb][2] + b0, 0.f);
            Tt[(r0 + 8) * TPIT + cn + 1] = fmaxf(c[ma][nb][3] + b1v, 0.f);
        }
    }
    __syncthreads();

    {
        int f = tid & 127;
        int half = tid >> 7;
        int base = half * 64;
        if (m0 + base < M) {
            float acc = 0.f;
            int curg = sbatch[base];
            for (int i = 0; i < 64; i++) {
                int gi = sbatch[base + i];
                if (gi < 0) break;
                if (gi != curg) {
                    atomicAdd(&poolp[(size_t)curg * FD + f], acc);
                    acc = 0.f;
                    curg = gi;
                }
                acc += Tt[(base + i) * TPIT + f];
            }
            if (curg >= 0) atomicAdd(&poolp[(size_t)curg * FD + f], acc);
        }
    }
}

// ---------------- GraphNorm (+relu): fp32 in, fp16 out ----------------
__global__ void __launch_bounds__(128) k_gnorm(
    const float* __restrict__ h,
    const float* __restrict__ scale, const float* __restrict__ weight,
    const float* __restrict__ bias)
{
    int g = blockIdx.x;
    int f = threadIdx.x;
    int s = g_gstart[g], e = g_gstart[g + 1];
    float cnt = fmaxf((float)(e - s), 1.0f);

    float sum = 0.f, sq = 0.f;
#pragma unroll 4
    for (int i = s; i < e; i++) {
        float v = h[(size_t)i * FD + f];
        sum += v;
        sq += v * v;
    }
    float mean = sum / cnt;
    float ms = mean * scale[f];
    float var = sq / cnt - 2.f * ms * mean + ms * ms;
    float inv = weight[f] * rsqrtf(var + 1e-8f);
    float bf = bias[f];

#pragma unroll 4
    for (int i = s; i < e; i++) {
        float o = fmaxf(inv * (h[(size_t)i * FD + f] - ms) + bf, 0.f);
        g_h16[(size_t)i * FD + f] = __float2half(o);
    }
}

// ---------------- final tiny GEMM: out[g, lofs+f] = pool[g]@W2 + cnt*b2 ----------------
__global__ void __launch_bounds__(128) k_pool2(
    const float* __restrict__ poolp,
    const float* __restrict__ w2, const float* __restrict__ b2,
    float* __restrict__ out, int lofs)
{
    __shared__ float sp[128];
    int g = blockIdx.x;
    int f = threadIdx.x;
    sp[f] = poolp[(size_t)g * FD + f];
    __syncthreads();
    if (f < TG) {
        int cnt = g_gstart[g + 1] - g_gstart[g];
        float o = (float)cnt * b2[f];
#pragma unroll 8
        for (int k = 0; k < FD; k++) o += sp[k] * w2[k * TG + f];
        out[(size_t)g * (LL * TG) + lofs + f] = o;
    }
}

// ---------------- launcher: two-stream DAG overlap ----------------
extern "C" void kernel_launch(void* const* d_in, const int* in_sizes, int n_in,
                              void* d_out, int out_size) {
    const float* x        = (const float*)d_in[0];
    const int*   edge     = (const int*)d_in[1];
    const int*   batch    = (const int*)d_in[2];
    const float* conv_w1  = (const float*)d_in[3];
    const float* conv_b1  = (const float*)d_in[4];
    const float* conv_w2  = (const float*)d_in[5];
    const float* conv_b2  = (const float*)d_in[6];
    const float* eps      = (const float*)d_in[7];
    const float* gn_scale = (const float*)d_in[8];
    const float* gn_weight= (const float*)d_in[9];
    const float* gn_bias  = (const float*)d_in[10];
    const float* proj_w1  = (const float*)d_in[11];
    const float* proj_b1  = (const float*)d_in[12];
    const float* proj_w2  = (const float*)d_in[13];
    const float* proj_b2  = (const float*)d_in[14];
    float* out = (float*)d_out;

    const int* src = edge;
    const int* dst = edge + EE;

    float *p_h, *p_pool;
    __half *p_h16, *p_a16, *p_t16, *p_wt16;
    cudaGetSymbolAddress((void**)&p_h, g_h);
    cudaGetSymbolAddress((void**)&p_pool, g_pool);
    cudaGetSymbolAddress((void**)&p_h16, g_h16);
    cudaGetSymbolAddress((void**)&p_a16, g_aggr16);
    cudaGetSymbolAddress((void**)&p_t16, g_t16);
    cudaGetSymbolAddress((void**)&p_wt16, g_wt16);

    cudaFuncSetAttribute(k_gemm16, cudaFuncAttributeMaxDynamicSharedMemorySize, GEMM_SMEM);
    cudaFuncSetAttribute(k_gemm_proj16, cudaFuncAttributeMaxDynamicSharedMemorySize, PROJ_SMEM);

    cudaStream_t s2;
    cudaStreamCreateWithFlags(&s2, cudaStreamNonBlocking);
    cudaEvent_t evStart, evPre, evG[LL], evPd[LL], evP[LL];
    cudaEventCreateWithFlags(&evStart, cudaEventDisableTiming);
    cudaEventCreateWithFlags(&evPre, cudaEventDisableTiming);
    for (int l = 0; l < LL; l++) {
        cudaEventCreateWithFlags(&evG[l], cudaEventDisableTiming);
        cudaEventCreateWithFlags(&evPd[l], cudaEventDisableTiming);
        cudaEventCreateWithFlags(&evP[l], cudaEventDisableTiming);
    }

    // fork: wtrans + x16 on s2, CSR build on main stream
    cudaEventRecord(evStart, 0);
    cudaStreamWaitEvent(s2, evStart, 0);
    k_wtrans<<<dim3(4, 4, 9), dim3(32, 8), 0, s2>>>(conv_w1, conv_w2, proj_w1);
    k_x16<<<(NN * FD / 2 + 255) / 256, 256, 0, s2>>>(x);
    cudaEventRecord(evPre, s2);

    k_init_zero<<<(LL * GG * FD + 255) / 256, 256>>>();
    k_hist<<<(EE + 255) / 256, 256>>>(dst);
    k_scan1<<<NB, 1024>>>();
    k_scan2<<<1, 128>>>();
    k_scan3<<<NB, 1024>>>();
    k_copycur<<<(NN + 255) / 256, 256>>>();
    k_bucket<<<(EE + 255) / 256, 256>>>(src, dst);
    k_gstart<<<3, 256>>>(batch);

    cudaStreamWaitEvent(0, evPre, 0);   // need h16 + wt16 before layer work

    for (int l = 0; l < LL; l++) {
        // main stream: aggr -> gemm1 -> gemm2 -> gnorm
        k_aggr16<<<(NN + 7) / 8, 256>>>(eps + l);
        k_gemm16<<<MTILES, 256, GEMM_SMEM>>>(p_a16,
                                             p_wt16 + (size_t)l * FD * FD,
                                             conv_b1 + (size_t)l * FD,
                                             p_t16, nullptr, NN, 1);
        k_gemm16<<<MTILES, 256, GEMM_SMEM>>>(p_t16,
                                             p_wt16 + (size_t)(3 + l) * FD * FD,
                                             conv_b2 + (size_t)l * FD,
                                             nullptr, p_h, NN, 0);
        // WAR: gnorm(l) overwrites g_h16, which proj(l-1) reads on s2
        if (l > 0) cudaStreamWaitEvent(0, evPd[l - 1], 0);
        k_gnorm<<<GG, 128>>>(p_h, gn_scale + (size_t)l * FD,
                             gn_weight + (size_t)l * FD, gn_bias + (size_t)l * FD);
        cudaEventRecord(evG[l], 0);

        // side stream: proj(l) + pool2(l), overlapped with next layer's aggr/gemms
        cudaStreamWaitEvent(s2, evG[l], 0);
        k_gemm_proj16<<<MTILES, 256, PROJ_SMEM, s2>>>(p_h16,
                                                      p_wt16 + (size_t)(6 + l) * FD * FD,
                                                      proj_b1 + (size_t)l * FD,
                                                      batch, p_pool + (size_t)l * GG * FD, NN);
        cudaEventRecord(evPd[l], s2);
        k_pool2<<<GG, 128, 0, s2>>>(p_pool + (size_t)l * GG * FD,
                                    proj_w2 + (size_t)l * FD * TG,
                                    proj_b2 + (size_t)l * TG, out, l * TG);
        cudaEventRecord(evP[l], s2);
    }

    // join all side-stream work back to origin stream
    for (int l = 0; l < LL; l++)
        cudaStreamWaitEvent(0, evP[l], 0);

    cudaEventDestroy(evStart);
    cudaEventDestroy(evPre);
    for (int l = 0; l < LL; l++) {
        cudaEventDestroy(evG[l]);
        cudaEventDestroy(evPd[l]);
        cudaEventDestroy(evP[l]);
    }
    cudaStreamDestroy(s2);
}

// round 12
// speedup vs baseline: 1.1446x; 1.0557x over previous
#include <cuda_runtime.h>
#include <cuda_fp16.h>
#include <cstdint>

#define NN 100000
#define EE 1600000
#define FD 128
#define GG 512
#define LL 3
#define TG 64
#define NB ((NN + 1023) / 1024)   /* 98 scan blocks */
#define MTILES ((NN + 127) / 128) /* 782 */

#define PH 136                     /* halves per SMEM row; conflict-free for LDSM */
#define PHB (PH * 2)               /* 272 bytes per row */
#define TILE_B (128 * PHB)         /* 34816 B per operand tile */
#define GEMM_SMEM (2 * TILE_B)     /* 69632 B */
#define TPIT 132                   /* fp32 pitch for proj T tile */
#define PROJ_SMEM (GEMM_SMEM + 512)

// ---------------- device scratch (no allocs allowed) ----------------
__device__ float  g_h[(size_t)NN * FD];       // fp32 conv2 output (gnorm input)
__device__ __half g_h16[(size_t)NN * FD];     // fp16 activations (gather/proj source)
__device__ __half g_aggr16[(size_t)NN * FD];
__device__ __half g_wt16[9 * FD * FD];        // pre-transposed weights [n][k], fp16
__device__ float  g_pool[LL * GG * FD];
__device__ int    g_deg[NN];
__device__ int    g_rowptr[NN + 1];
__device__ int    g_cursor[NN];
__device__ int    g_bsum[NB];
__device__ int    g_boff[NB];
__device__ int    g_srcsorted[EE];
__device__ int    g_gstart[GG + 1];

__device__ __forceinline__ uint32_t smem_u32(const void* p) {
    uint32_t a;
    asm("{ .reg .u64 t; cvta.to.shared.u64 t, %1; cvt.u32.u64 %0, t; }" : "=r"(a) : "l"(p));
    return a;
}
__device__ __forceinline__ void cp16(uint32_t dst, const void* src) {
    asm volatile("cp.async.cg.shared.global [%0], [%1], 16;"
                 :: "r"(dst), "l"(src) : "memory");
}
__device__ __forceinline__ void mma_f16(float* c, const uint32_t* a, const uint32_t* b) {
    asm volatile(
        "mma.sync.aligned.m16n8k16.row.col.f32.f16.f16.f32 "
        "{%0,%1,%2,%3}, {%4,%5,%6,%7}, {%8,%9}, {%0,%1,%2,%3};"
        : "+f"(c[0]), "+f"(c[1]), "+f"(c[2]), "+f"(c[3])
        : "r"(a[0]), "r"(a[1]), "r"(a[2]), "r"(a[3]), "r"(b[0]), "r"(b[1]));
}
__device__ __forceinline__ void ldsm4(uint32_t* r, uint32_t addr) {
    asm volatile("ldmatrix.sync.aligned.m8n8.x4.shared.b16 {%0,%1,%2,%3}, [%4];"
                 : "=r"(r[0]), "=r"(r[1]), "=r"(r[2]), "=r"(r[3]) : "r"(addr));
}
__device__ __forceinline__ void acc_h4(float4& acc, uint2 v) {
    float2 f0 = __half22float2(*(const __half2*)&v.x);
    float2 f1 = __half22float2(*(const __half2*)&v.y);
    acc.x += f0.x; acc.y += f0.y; acc.z += f1.x; acc.w += f1.y;
}

// ---------------- init / CSR build ----------------
__global__ void k_init_zero() {
    int i = blockIdx.x * 256 + threadIdx.x;
    if (i < NN) g_deg[i] = 0;
    if (i < LL * GG * FD) g_pool[i] = 0.f;
}
__global__ void k_hist(const int* __restrict__ dst) {
    int e = blockIdx.x * 256 + threadIdx.x;
    if (e < EE) atomicAdd(&g_deg[dst[e]], 1);
}
__global__ void k_scan1() {
    __shared__ int sh[1024];
    int i = blockIdx.x * 1024 + threadIdx.x;
    int v = (i < NN) ? g_deg[i] : 0;
    sh[threadIdx.x] = v;
    __syncthreads();
    for (int off = 1; off < 1024; off <<= 1) {
        int t = sh[threadIdx.x];
        int a = (threadIdx.x >= off) ? sh[threadIdx.x - off] : 0;
        __syncthreads();
        sh[threadIdx.x] = t + a;
        __syncthreads();
    }
    if (i < NN) g_rowptr[i + 1] = sh[threadIdx.x];
    if (threadIdx.x == 1023) g_bsum[blockIdx.x] = sh[1023];
}
__global__ void k_scan2() {
    __shared__ int sh[128];
    int t = threadIdx.x;
    int v = (t < NB) ? g_bsum[t] : 0;
    sh[t] = v;
    __syncthreads();
    for (int off = 1; off < 128; off <<= 1) {
        int x = sh[t];
        int a = (t >= off) ? sh[t - off] : 0;
        __syncthreads();
        sh[t] = x + a;
        __syncthreads();
    }
    if (t < NB) g_boff[t] = sh[t] - v;
}
__global__ void k_scan3() {
    int i = blockIdx.x * 1024 + threadIdx.x;
    if (i < NN) g_rowptr[i + 1] += g_boff[blockIdx.x];
    if (i == 0) g_rowptr[0] = 0;
}
__global__ void k_copycur() {
    int i = blockIdx.x * 256 + threadIdx.x;
    if (i < NN) g_cursor[i] = g_rowptr[i];
}
__global__ void k_bucket(const int* __restrict__ src, const int* __restrict__ dst) {
    int e = blockIdx.x * 256 + threadIdx.x;
    if (e < EE) {
        int d = dst[e];
        int pos = atomicAdd(&g_cursor[d], 1);
        g_srcsorted[pos] = src[e];
    }
}
__global__ void k_gstart(const int* __restrict__ batch) {
    int g = blockIdx.x * 256 + threadIdx.x;
    if (g <= GG) {
        int lo = 0, hi = NN;
        while (lo < hi) {
            int mid = (lo + hi) >> 1;
            if (batch[mid] < g) lo = mid + 1; else hi = mid;
        }
        g_gstart[g] = lo;
    }
}

// ---------------- x -> fp16 ----------------
__global__ void k_x16(const float* __restrict__ x) {
    int i = blockIdx.x * 256 + threadIdx.x;
    if (i < NN * FD / 2) {
        float2 v = ((const float2*)x)[i];
        ((__half2*)g_h16)[i] = __floats2half2_rn(v.x, v.y);
    }
}

// ---------------- weight transpose -> fp16 [n][k] ----------------
__global__ void k_wtrans(const float* __restrict__ w1, const float* __restrict__ w2,
                         const float* __restrict__ w3) {
    __shared__ float t[32][33];
    int mi = blockIdx.z;
    const float* src = (mi < 3) ? (w1 + (size_t)mi * FD * FD)
                     : (mi < 6) ? (w2 + (size_t)(mi - 3) * FD * FD)
                                : (w3 + (size_t)(mi - 6) * FD * FD);
    __half* dst = g_wt16 + (size_t)mi * FD * FD;
    int x0 = blockIdx.x * 32, y0 = blockIdx.y * 32;
    for (int dy = threadIdx.y; dy < 32; dy += 8)
        t[dy][threadIdx.x] = src[(size_t)(y0 + dy) * FD + x0 + threadIdx.x];
    __syncthreads();
    for (int dy = threadIdx.y; dy < 32; dy += 8)
        dst[(size_t)(x0 + dy) * FD + y0 + threadIdx.x] = __float2half(t[threadIdx.x][dy]);
}

// ---------------- aggregation + GIN combine (fp16 in, fp16 out) ----------------
__global__ void __launch_bounds__(256) k_aggr16(const float* __restrict__ epsp) {
    int node = blockIdx.x * 8 + (threadIdx.x >> 5);
    if (node >= NN) return;
    int lane = threadIdx.x & 31;
    int s = g_rowptr[node], e = g_rowptr[node + 1];
    float alpha = 1.0f + epsp[0];
    const uint2* hp = (const uint2*)g_h16;
    uint2 hv = hp[(size_t)node * 32 + lane];
    float2 f0 = __half22float2(*(const __half2*)&hv.x);
    float2 f1 = __half22float2(*(const __half2*)&hv.y);
    float4 acc = make_float4(alpha * f0.x, alpha * f0.y, alpha * f1.x, alpha * f1.y);
    int j = s;
    for (; j + 3 < e; j += 4) {
        int s0 = g_srcsorted[j],     s1 = g_srcsorted[j + 1];
        int s2 = g_srcsorted[j + 2], s3 = g_srcsorted[j + 3];
        uint2 v0 = hp[(size_t)s0 * 32 + lane];
        uint2 v1 = hp[(size_t)s1 * 32 + lane];
        uint2 v2 = hp[(size_t)s2 * 32 + lane];
        uint2 v3 = hp[(size_t)s3 * 32 + lane];
        acc_h4(acc, v0); acc_h4(acc, v1); acc_h4(acc, v2); acc_h4(acc, v3);
    }
    for (; j < e; j++) acc_h4(acc, hp[(size_t)g_srcsorted[j] * 32 + lane]);
    uint2 o;
    *(__half2*)&o.x = __floats2half2_rn(acc.x, acc.y);
    *(__half2*)&o.y = __floats2half2_rn(acc.z, acc.w);
    ((uint2*)g_aggr16)[(size_t)node * 32 + lane] = o;
}

// ---------------- fused GIN MLP: C32 = relu(A@W1^T + b1)@W2^T + b2 ----------------
// T tile lives in SMEM (fp16, replaces A after mainloop1); W2 prefetched into W1 slot.
__global__ void __launch_bounds__(256) k_gin16(
    const __half* __restrict__ A16,
    const __half* __restrict__ W1t, const float* __restrict__ b1p,
    const __half* __restrict__ W2t, const float* __restrict__ b2p,
    float* __restrict__ C32, int M)
{
    extern __shared__ __half smem[];
    uint32_t sb = smem_u32(smem);
    int tid = threadIdx.x;
    int w = tid >> 5, lane = tid & 31;
    int m0 = blockIdx.x * 128;

    // stage A (side 0) + W1 (side 1): 4096 x 16B
#pragma unroll
    for (int i = 0; i < 16; i++) {
        int o = i * 256 + tid;
        int side = o >> 11;
        int idx = o & 2047;
        int row = idx >> 4;
        int q = idx & 15;
        uint32_t dst = sb + (uint32_t)(side * TILE_B + row * PHB + q * 16);
        if (side == 0) {
            int m = m0 + row;
            cp16(dst, A16 + ((m < M) ? ((size_t)m * FD + q * 8) : (size_t)(q * 8)));
        } else {
            cp16(dst, W1t + (size_t)row * FD + q * 8);
        }
    }
    asm volatile("cp.async.commit_group;" ::: "memory");
    asm volatile("cp.async.wait_group 0;" ::: "memory");
    __syncthreads();

    int warpM = w >> 2, warpN = w & 3;
    int g = lane >> 2, t = lane & 3;
    int sub = lane >> 3, j8 = lane & 7;

    uint32_t aBase = sb + (uint32_t)((warpM * 64 + j8 + (sub & 1) * 8) * PHB + (sub >> 1) * 16);
    uint32_t bBase = sb + (uint32_t)(TILE_B + (warpN * 32 + j8 + (sub >> 1) * 8) * PHB + (sub & 1) * 16);

    float c[4][4][4];
#pragma unroll
    for (int ma = 0; ma < 4; ma++)
#pragma unroll
        for (int nb = 0; nb < 4; nb++)
#pragma unroll
            for (int r = 0; r < 4; r++) c[ma][nb][r] = 0.f;

    // ---- mainloop 1: A @ W1^T ----
#pragma unroll
    for (int ks = 0; ks < 8; ks++) {
        uint32_t kofs = ks * 32;
        uint32_t af[4][4];
#pragma unroll
        for (int ma = 0; ma < 4; ma++)
            ldsm4(af[ma], aBase + ma * 16 * PHB + kofs);
        uint32_t bf01[4], bf23[4];
        ldsm4(bf01, bBase + kofs);
        ldsm4(bf23, bBase + 16 * PHB + kofs);
#pragma unroll
        for (int ma = 0; ma < 4; ma++) {
            mma_f16(c[ma][0], af[ma], &bf01[0]);
            mma_f16(c[ma][1], af[ma], &bf01[2]);
            mma_f16(c[ma][2], af[ma], &bf23[0]);
            mma_f16(c[ma][3], af[ma], &bf23[2]);
        }
    }
    __syncthreads();   // all reads of A/W1 done

    // prefetch W2 into the (dead) W1 slot, overlapped with T writes
#pragma unroll
    for (int i = 0; i < 8; i++) {
        int o = i * 256 + tid;       // 0..2047
        int row = o >> 4;
        int q = o & 15;
        cp16(sb + (uint32_t)(TILE_B + row * PHB + q * 16), W2t + (size_t)row * FD + q * 8);
    }
    asm volatile("cp.async.commit_group;" ::: "memory");

    // T = fp16(relu(acc + b1)) into the (dead) A slot; conflict-free half2 stores
#pragma unroll
    for (int ma = 0; ma < 4; ma++) {
        int r0 = warpM * 64 + ma * 16 + g;
#pragma unroll
        for (int nb = 0; nb < 4; nb++) {
            int cn = warpN * 32 + nb * 8 + 2 * t;
            float b0 = b1p[cn], b1v = b1p[cn + 1];
            *(__half2*)(smem + r0 * PH + cn) =
                __floats2half2_rn(fmaxf(c[ma][nb][0] + b0, 0.f), fmaxf(c[ma][nb][1] + b1v, 0.f));
            *(__half2*)(smem + (r0 + 8) * PH + cn) =
                __floats2half2_rn(fmaxf(c[ma][nb][2] + b0, 0.f), fmaxf(c[ma][nb][3] + b1v, 0.f));
#pragma unroll
            for (int r = 0; r < 4; r++) c[ma][nb][r] = 0.f;
        }
    }
    asm volatile("cp.async.wait_group 0;" ::: "memory");
    __syncthreads();

    // ---- mainloop 2: T @ W2^T (identical addressing) ----
#pragma unroll
    for (int ks = 0; ks < 8; ks++) {
        uint32_t kofs = ks * 32;
        uint32_t af[4][4];
#pragma unroll
        for (int ma = 0; ma < 4; ma++)
            ldsm4(af[ma], aBase + ma * 16 * PHB + kofs);
        uint32_t bf01[4], bf23[4];
        ldsm4(bf01, bBase + kofs);
        ldsm4(bf23, bBase + 16 * PHB + kofs);
#pragma unroll
        for (int ma = 0; ma < 4; ma++) {
            mma_f16(c[ma][0], af[ma], &bf01[0]);
            mma_f16(c[ma][1], af[ma], &bf01[2]);
            mma_f16(c[ma][2], af[ma], &bf23[0]);
            mma_f16(c[ma][3], af[ma], &bf23[2]);
        }
    }

    // epilogue: h = acc + b2 (fp32; gnorm consumes)
#pragma unroll
    for (int ma = 0; ma < 4; ma++) {
        int r0 = m0 + warpM * 64 + ma * 16 + g;
#pragma unroll
        for (int nb = 0; nb < 4; nb++) {
            int cn = warpN * 32 + nb * 8 + 2 * t;
            float b0 = b2p[cn], b1v = b2p[cn + 1];
            if (r0 < M)
                *(float2*)&C32[(size_t)r0 * FD + cn] =
                    make_float2(c[ma][nb][0] + b0, c[ma][nb][1] + b1v);
            if (r0 + 8 < M)
                *(float2*)&C32[(size_t)(r0 + 8) * FD + cn] =
                    make_float2(c[ma][nb][2] + b0, c[ma][nb][3] + b1v);
        }
    }
}

// ---------------- proj GEMM (fp16, LDSM) fused with pool partial-sums ----------------
__global__ void __launch_bounds__(256) k_gemm_proj16(
    const __half* __restrict__ A16, const __half* __restrict__ Wt16,
    const float* __restrict__ bias,
    const int* __restrict__ batch, float* __restrict__ poolp, int M)
{
    extern __shared__ __half smem[];
    uint32_t sb = smem_u32(smem);
    float* Tt = (float*)smem;
    int* sbatch = (int*)((char*)smem + GEMM_SMEM);
    int tid = threadIdx.x;
    int w = tid >> 5, lane = tid & 31;
    int m0 = blockIdx.x * 128;

#pragma unroll
    for (int i = 0; i < 16; i++) {
        int o = i * 256 + tid;
        int side = o >> 11;
        int idx = o & 2047;
        int row = idx >> 4;
        int q = idx & 15;
        uint32_t dst = sb + (uint32_t)(side * TILE_B + row * PHB + q * 16);
        if (side == 0) {
            int m = m0 + row;
            cp16(dst, A16 + ((m < M) ? ((size_t)m * FD + q * 8) : (size_t)(q * 8)));
        } else {
            cp16(dst, Wt16 + (size_t)row * FD + q * 8);
        }
    }
    asm volatile("cp.async.commit_group;" ::: "memory");
    asm volatile("cp.async.wait_group 0;" ::: "memory");
    __syncthreads();

    int warpM = w >> 2, warpN = w & 3;
    int g = lane >> 2, t = lane & 3;
    int sub = lane >> 3, j8 = lane & 7;

    uint32_t aBase = sb + (uint32_t)((warpM * 64 + j8 + (sub & 1) * 8) * PHB + (sub >> 1) * 16);
    uint32_t bBase = sb + (uint32_t)(TILE_B + (warpN * 32 + j8 + (sub >> 1) * 8) * PHB + (sub & 1) * 16);

    float c[4][4][4];
#pragma unroll
    for (int ma = 0; ma < 4; ma++)
#pragma unroll
        for (int nb = 0; nb < 4; nb++)
#pragma unroll
            for (int r = 0; r < 4; r++) c[ma][nb][r] = 0.f;

#pragma unroll
    for (int ks = 0; ks < 8; ks++) {
        uint32_t kofs = ks * 32;
        uint32_t af[4][4];
#pragma unroll
        for (int ma = 0; ma < 4; ma++)
            ldsm4(af[ma], aBase + ma * 16 * PHB + kofs);
        uint32_t bf01[4], bf23[4];
        ldsm4(bf01, bBase + kofs);
        ldsm4(bf23, bBase + 16 * PHB + kofs);
#pragma unroll
        for (int ma = 0; ma < 4; ma++) {
            mma_f16(c[ma][0], af[ma], &bf01[0]);
            mma_f16(c[ma][1], af[ma], &bf01[2]);
            mma_f16(c[ma][2], af[ma], &bf23[0]);
            mma_f16(c[ma][3], af[ma], &bf23[2]);
        }
    }
    __syncthreads();   // operands dead; reuse SMEM for T tile

    if (tid < 128) sbatch[tid] = (m0 + tid < M) ? batch[m0 + tid] : -1;
#pragma unroll
    for (int ma = 0; ma < 4; ma++) {
        int r0 = warpM * 64 + ma * 16 + g;
#pragma unroll
        for (int nb = 0; nb < 4; nb++) {
            int cn = warpN * 32 + nb * 8 + 2 * t;
            float b0 = bias[cn], b1v = bias[cn + 1];
            Tt[r0 * TPIT + cn]           = fmaxf(c[ma][nb][0] + b0, 0.f);
            Tt[r0 * TPIT + cn + 1]       = fmaxf(c[ma][nb][1] + b1v, 0.f);
            Tt[(r0 + 8) * TPIT + cn]     = fmaxf(c[ma][nb][2] + b0, 0.f);
            Tt[(r0 + 8) * TPIT + cn + 1] = fmaxf(c[ma][nb][3] + b1v, 0.f);
        }
    }
    __syncthreads();

    {
        int f = tid & 127;
        int half = tid >> 7;
        int base = half * 64;
        if (m0 + base < M) {
            float acc = 0.f;
            int curg = sbatch[base];
            for (int i = 0; i < 64; i++) {
                int gi = sbatch[base + i];
                if (gi < 0) break;
                if (gi != curg) {
                    atomicAdd(&poolp[(size_t)curg * FD + f], acc);
                    acc = 0.f;
                    curg = gi;
                }
                acc += Tt[(base + i) * TPIT + f];
            }
            if (curg >= 0) atomicAdd(&poolp[(size_t)curg * FD + f], acc);
        }
    }
}

// ---------------- GraphNorm (+relu): fp32 in, fp16 out ----------------
__global__ void __launch_bounds__(128) k_gnorm(
    const float* __restrict__ h,
    const float* __restrict__ scale, const float* __restrict__ weight,
    const float* __restrict__ bias)
{
    int g = blockIdx.x;
    int f = threadIdx.x;
    int s = g_gstart[g], e = g_gstart[g + 1];
    float cnt = fmaxf((float)(e - s), 1.0f);

    float sum = 0.f, sq = 0.f;
#pragma unroll 4
    for (int i = s; i < e; i++) {
        float v = h[(size_t)i * FD + f];
        sum += v;
        sq += v * v;
    }
    float mean = sum / cnt;
    float ms = mean * scale[f];
    float var = sq / cnt - 2.f * ms * mean + ms * ms;
    float inv = weight[f] * rsqrtf(var + 1e-8f);
    float bf = bias[f];

#pragma unroll 4
    for (int i = s; i < e; i++) {
        float o = fmaxf(inv * (h[(size_t)i * FD + f] - ms) + bf, 0.f);
        g_h16[(size_t)i * FD + f] = __float2half(o);
    }
}

// ---------------- final tiny GEMM ----------------
__global__ void __launch_bounds__(128) k_pool2(
    const float* __restrict__ poolp,
    const float* __restrict__ w2, const float* __restrict__ b2,
    float* __restrict__ out, int lofs)
{
    __shared__ float sp[128];
    int g = blockIdx.x;
    int f = threadIdx.x;
    sp[f] = poolp[(size_t)g * FD + f];
    __syncthreads();
    if (f < TG) {
        int cnt = g_gstart[g + 1] - g_gstart[g];
        float o = (float)cnt * b2[f];
#pragma unroll 8
        for (int k = 0; k < FD; k++) o += sp[k] * w2[k * TG + f];
        out[(size_t)g * (LL * TG) + lofs + f] = o;
    }
}

// ---------------- launcher: two-stream DAG overlap ----------------
extern "C" void kernel_launch(void* const* d_in, const int* in_sizes, int n_in,
                              void* d_out, int out_size) {
    const float* x        = (const float*)d_in[0];
    const int*   edge     = (const int*)d_in[1];
    const int*   batch    = (const int*)d_in[2];
    const float* conv_w1  = (const float*)d_in[3];
    const float* conv_b1  = (const float*)d_in[4];
    const float* conv_w2  = (const float*)d_in[5];
    const float* conv_b2  = (const float*)d_in[6];
    const float* eps      = (const float*)d_in[7];
    const float* gn_scale = (const float*)d_in[8];
    const float* gn_weight= (const float*)d_in[9];
    const float* gn_bias  = (const float*)d_in[10];
    const float* proj_w1  = (const float*)d_in[11];
    const float* proj_b1  = (const float*)d_in[12];
    const float* proj_w2  = (const float*)d_in[13];
    const float* proj_b2  = (const float*)d_in[14];
    float* out = (float*)d_out;

    const int* src = edge;
    const int* dst = edge + EE;

    float *p_h, *p_pool;
    __half *p_h16, *p_a16, *p_wt16;
    cudaGetSymbolAddress((void**)&p_h, g_h);
    cudaGetSymbolAddress((void**)&p_pool, g_pool);
    cudaGetSymbolAddress((void**)&p_h16, g_h16);
    cudaGetSymbolAddress((void**)&p_a16, g_aggr16);
    cudaGetSymbolAddress((void**)&p_wt16, g_wt16);

    cudaFuncSetAttribute(k_gin16, cudaFuncAttributeMaxDynamicSharedMemorySize, GEMM_SMEM);
    cudaFuncSetAttribute(k_gemm_proj16, cudaFuncAttributeMaxDynamicSharedMemorySize, PROJ_SMEM);

    cudaStream_t s2;
    cudaStreamCreateWithFlags(&s2, cudaStreamNonBlocking);
    cudaEvent_t evStart, evPre, evG[LL], evPd[LL], evP[LL];
    cudaEventCreateWithFlags(&evStart, cudaEventDisableTiming);
    cudaEventCreateWithFlags(&evPre, cudaEventDisableTiming);
    for (int l = 0; l < LL; l++) {
        cudaEventCreateWithFlags(&evG[l], cudaEventDisableTiming);
        cudaEventCreateWithFlags(&evPd[l], cudaEventDisableTiming);
        cudaEventCreateWithFlags(&evP[l], cudaEventDisableTiming);
    }

    // fork: wtrans + x16 on s2, CSR build on main stream
    cudaEventRecord(evStart, 0);
    cudaStreamWaitEvent(s2, evStart, 0);
    k_wtrans<<<dim3(4, 4, 9), dim3(32, 8), 0, s2>>>(conv_w1, conv_w2, proj_w1);
    k_x16<<<(NN * FD / 2 + 255) / 256, 256, 0, s2>>>(x);
    cudaEventRecord(evPre, s2);

    k_init_zero<<<(LL * GG * FD + 255) / 256, 256>>>();
    k_hist<<<(EE + 255) / 256, 256>>>(dst);
    k_scan1<<<NB, 1024>>>();
    k_scan2<<<1, 128>>>();
    k_scan3<<<NB, 1024>>>();
    k_copycur<<<(NN + 255) / 256, 256>>>();
    k_bucket<<<(EE + 255) / 256, 256>>>(src, dst);
    k_gstart<<<3, 256>>>(batch);

    cudaStreamWaitEvent(0, evPre, 0);   // need h16 + wt16 before layer work

    for (int l = 0; l < LL; l++) {
        // main stream: aggr -> fused MLP -> gnorm
        k_aggr16<<<(NN + 7) / 8, 256>>>(eps + l);
        k_gin16<<<MTILES, 256, GEMM_SMEM>>>(p_a16,
                                            p_wt16 + (size_t)l * FD * FD,
                                            conv_b1 + (size_t)l * FD,
                                            p_wt16 + (size_t)(3 + l) * FD * FD,
                                            conv_b2 + (size_t)l * FD, p_h, NN);
        // WAR: gnorm(l) overwrites g_h16, which proj(l-1) reads on s2
        if (l > 0) cudaStreamWaitEvent(0, evPd[l - 1], 0);
        k_gnorm<<<GG, 128>>>(p_h, gn_scale + (size_t)l * FD,
                             gn_weight + (size_t)l * FD, gn_bias + (size_t)l * FD);
        cudaEventRecord(evG[l], 0);

        // side stream: proj(l) + pool2(l), overlapped with next layer
        cudaStreamWaitEvent(s2, evG[l], 0);
        k_gemm_proj16<<<MTILES, 256, PROJ_SMEM, s2>>>(p_h16,
                                                      p_wt16 + (size_t)(6 + l) * FD * FD,
                                                      proj_b1 + (size_t)l * FD,
                                                      batch, p_pool + (size_t)l * GG * FD, NN);
        cudaEventRecord(evPd[l], s2);
        k_pool2<<<GG, 128, 0, s2>>>(p_pool + (size_t)l * GG * FD,
                                    proj_w2 + (size_t)l * FD * TG,
                                    proj_b2 + (size_t)l * TG, out, l * TG);
        cudaEventRecord(evP[l], s2);
    }

    for (int l = 0; l < LL; l++)
        cudaStreamWaitEvent(0, evP[l], 0);

    cudaEventDestroy(evStart);
    cudaEventDestroy(evPre);
    for (int l = 0; l < LL; l++) {
        cudaEventDestroy(evG[l]);
        cudaEventDestroy(evPd[l]);
        cudaEventDestroy(evP[l]);
    }
    cudaStreamDestroy(s2);
}

// round 13
// speedup vs baseline: 1.1980x; 1.0466x over previous
#include <cuda_runtime.h>
#include <cuda_fp16.h>
#include <cstdint>

#define NN 100000
#define EE 1600000
#define FD 128
#define GG 512
#define LL 3
#define TG 64
#define NB ((NN + 1023) / 1024)   /* 98 scan blocks */
#define MTILES ((NN + 127) / 128) /* 782 */

#define PH 136                     /* halves per SMEM row; conflict-free for LDSM */
#define PHB (PH * 2)               /* 272 bytes per row */
#define TILE_B (128 * PHB)         /* 34816 B per operand tile */
#define GEMM_SMEM (2 * TILE_B)     /* 69632 B */
#define TPIT 132                   /* fp32 pitch for proj T tile */
#define PROJ_SMEM (GEMM_SMEM + 512)

// ---------------- device scratch (no allocs allowed) ----------------
__device__ __half g_hb16[(size_t)NN * FD];    // fp16 conv2 output (gnorm input)
__device__ __half g_h16[(size_t)NN * FD];     // fp16 activations (gather/proj source)
__device__ __half g_aggr16[(size_t)NN * FD];
__device__ __half g_wt16[9 * FD * FD];        // pre-transposed weights [n][k], fp16
__device__ float  g_pool[LL * GG * FD];
__device__ int    g_deg[NN];
__device__ int    g_rowptr[NN + 1];
__device__ int    g_cursor[NN];
__device__ int    g_bsum[NB];
__device__ int    g_boff[NB];
__device__ int    g_srcsorted[EE];
__device__ int    g_gstart[GG + 1];

__device__ __forceinline__ uint32_t smem_u32(const void* p) {
    uint32_t a;
    asm("{ .reg .u64 t; cvta.to.shared.u64 t, %1; cvt.u32.u64 %0, t; }" : "=r"(a) : "l"(p));
    return a;
}
__device__ __forceinline__ void cp16(uint32_t dst, const void* src) {
    asm volatile("cp.async.cg.shared.global [%0], [%1], 16;"
                 :: "r"(dst), "l"(src) : "memory");
}
__device__ __forceinline__ void mma_f16(float* c, const uint32_t* a, const uint32_t* b) {
    asm volatile(
        "mma.sync.aligned.m16n8k16.row.col.f32.f16.f16.f32 "
        "{%0,%1,%2,%3}, {%4,%5,%6,%7}, {%8,%9}, {%0,%1,%2,%3};"
        : "+f"(c[0]), "+f"(c[1]), "+f"(c[2]), "+f"(c[3])
        : "r"(a[0]), "r"(a[1]), "r"(a[2]), "r"(a[3]), "r"(b[0]), "r"(b[1]));
}
__device__ __forceinline__ void ldsm4(uint32_t* r, uint32_t addr) {
    asm volatile("ldmatrix.sync.aligned.m8n8.x4.shared.b16 {%0,%1,%2,%3}, [%4];"
                 : "=r"(r[0]), "=r"(r[1]), "=r"(r[2]), "=r"(r[3]) : "r"(addr));
}
__device__ __forceinline__ void acc_h4(float4& acc, uint2 v) {
    float2 f0 = __half22float2(*(const __half2*)&v.x);
    float2 f1 = __half22float2(*(const __half2*)&v.y);
    acc.x += f0.x; acc.y += f0.y; acc.z += f1.x; acc.w += f1.y;
}

// ---------------- init / CSR build ----------------
__global__ void k_init_zero() {
    int i = blockIdx.x * 256 + threadIdx.x;
    if (i < NN) g_deg[i] = 0;
    if (i < LL * GG * FD) g_pool[i] = 0.f;
}
__global__ void k_hist(const int* __restrict__ dst) {
    int e = blockIdx.x * 256 + threadIdx.x;
    if (e < EE) atomicAdd(&g_deg[dst[e]], 1);
}
__global__ void k_scan1() {
    __shared__ int sh[1024];
    int i = blockIdx.x * 1024 + threadIdx.x;
    int v = (i < NN) ? g_deg[i] : 0;
    sh[threadIdx.x] = v;
    __syncthreads();
    for (int off = 1; off < 1024; off <<= 1) {
        int t = sh[threadIdx.x];
        int a = (threadIdx.x >= off) ? sh[threadIdx.x - off] : 0;
        __syncthreads();
        sh[threadIdx.x] = t + a;
        __syncthreads();
    }
    if (i < NN) g_rowptr[i + 1] = sh[threadIdx.x];
    if (threadIdx.x == 1023) g_bsum[blockIdx.x] = sh[1023];
}
__global__ void k_scan2() {
    __shared__ int sh[128];
    int t = threadIdx.x;
    int v = (t < NB) ? g_bsum[t] : 0;
    sh[t] = v;
    __syncthreads();
    for (int off = 1; off < 128; off <<= 1) {
        int x = sh[t];
        int a = (t >= off) ? sh[t - off] : 0;
        __syncthreads();
        sh[t] = x + a;
        __syncthreads();
    }
    if (t < NB) g_boff[t] = sh[t] - v;
}
__global__ void k_scan3() {
    int i = blockIdx.x * 1024 + threadIdx.x;
    if (i < NN) {
        int v = g_rowptr[i + 1] + g_boff[blockIdx.x];
        g_rowptr[i + 1] = v;
        if (i + 1 < NN) g_cursor[i + 1] = v;   // cursor = exclusive rowptr
    }
    if (i == 0) { g_rowptr[0] = 0; g_cursor[0] = 0; }
}
__global__ void k_bucket(const int* __restrict__ src, const int* __restrict__ dst) {
    int e = blockIdx.x * 256 + threadIdx.x;
    if (e < EE) {
        int d = dst[e];
        int pos = atomicAdd(&g_cursor[d], 1);
        g_srcsorted[pos] = src[e];
    }
}
__global__ void k_gstart(const int* __restrict__ batch) {
    int g = blockIdx.x * 256 + threadIdx.x;
    if (g <= GG) {
        int lo = 0, hi = NN;
        while (lo < hi) {
            int mid = (lo + hi) >> 1;
            if (batch[mid] < g) lo = mid + 1; else hi = mid;
        }
        g_gstart[g] = lo;
    }
}

// ---------------- x -> fp16 ----------------
__global__ void k_x16(const float* __restrict__ x) {
    int i = blockIdx.x * 256 + threadIdx.x;
    if (i < NN * FD / 2) {
        float2 v = ((const float2*)x)[i];
        ((__half2*)g_h16)[i] = __floats2half2_rn(v.x, v.y);
    }
}

// ---------------- weight transpose -> fp16 [n][k] ----------------
__global__ void k_wtrans(const float* __restrict__ w1, const float* __restrict__ w2,
                         const float* __restrict__ w3) {
    __shared__ float t[32][33];
    int mi = blockIdx.z;
    const float* src = (mi < 3) ? (w1 + (size_t)mi * FD * FD)
                     : (mi < 6) ? (w2 + (size_t)(mi - 3) * FD * FD)
                                : (w3 + (size_t)(mi - 6) * FD * FD);
    __half* dst = g_wt16 + (size_t)mi * FD * FD;
    int x0 = blockIdx.x * 32, y0 = blockIdx.y * 32;
    for (int dy = threadIdx.y; dy < 32; dy += 8)
        t[dy][threadIdx.x] = src[(size_t)(y0 + dy) * FD + x0 + threadIdx.x];
    __syncthreads();
    for (int dy = threadIdx.y; dy < 32; dy += 8)
        dst[(size_t)(x0 + dy) * FD + y0 + threadIdx.x] = __float2half(t[threadIdx.x][dy]);
}

// ---------------- aggregation + GIN combine (fp16 in, fp16 out) ----------------
__global__ void __launch_bounds__(256) k_aggr16(const float* __restrict__ epsp) {
    int node = blockIdx.x * 8 + (threadIdx.x >> 5);
    if (node >= NN) return;
    int lane = threadIdx.x & 31;
    int s = g_rowptr[node], e = g_rowptr[node + 1];
    float alpha = 1.0f + epsp[0];
    const uint2* hp = (const uint2*)g_h16;
    uint2 hv = hp[(size_t)node * 32 + lane];
    float2 f0 = __half22float2(*(const __half2*)&hv.x);
    float2 f1 = __half22float2(*(const __half2*)&hv.y);
    float4 acc = make_float4(alpha * f0.x, alpha * f0.y, alpha * f1.x, alpha * f1.y);
    int j = s;
    for (; j + 3 < e; j += 4) {
        int s0 = g_srcsorted[j],     s1 = g_srcsorted[j + 1];
        int s2 = g_srcsorted[j + 2], s3 = g_srcsorted[j + 3];
        uint2 v0 = hp[(size_t)s0 * 32 + lane];
        uint2 v1 = hp[(size_t)s1 * 32 + lane];
        uint2 v2 = hp[(size_t)s2 * 32 + lane];
        uint2 v3 = hp[(size_t)s3 * 32 + lane];
        acc_h4(acc, v0); acc_h4(acc, v1); acc_h4(acc, v2); acc_h4(acc, v3);
    }
    for (; j < e; j++) acc_h4(acc, hp[(size_t)g_srcsorted[j] * 32 + lane]);
    uint2 o;
    *(__half2*)&o.x = __floats2half2_rn(acc.x, acc.y);
    *(__half2*)&o.y = __floats2half2_rn(acc.z, acc.w);
    ((uint2*)g_aggr16)[(size_t)node * 32 + lane] = o;
}

// ---------------- fused GIN MLP: hb16 = fp16(relu(A@W1^T + b1)@W2^T + b2) ----------------
__global__ void __launch_bounds__(256) k_gin16(
    const __half* __restrict__ A16,
    const __half* __restrict__ W1t, const float* __restrict__ b1p,
    const __half* __restrict__ W2t, const float* __restrict__ b2p,
    __half* __restrict__ C16, int M)
{
    extern __shared__ __half smem[];
    uint32_t sb = smem_u32(smem);
    int tid = threadIdx.x;
    int w = tid >> 5, lane = tid & 31;
    int m0 = blockIdx.x * 128;

    // stage A (side 0) + W1 (side 1): 4096 x 16B
#pragma unroll
    for (int i = 0; i < 16; i++) {
        int o = i * 256 + tid;
        int side = o >> 11;
        int idx = o & 2047;
        int row = idx >> 4;
        int q = idx & 15;
        uint32_t dst = sb + (uint32_t)(side * TILE_B + row * PHB + q * 16);
        if (side == 0) {
            int m = m0 + row;
            cp16(dst, A16 + ((m < M) ? ((size_t)m * FD + q * 8) : (size_t)(q * 8)));
        } else {
            cp16(dst, W1t + (size_t)row * FD + q * 8);
        }
    }
    asm volatile("cp.async.commit_group;" ::: "memory");
    asm volatile("cp.async.wait_group 0;" ::: "memory");
    __syncthreads();

    int warpM = w >> 2, warpN = w & 3;
    int g = lane >> 2, t = lane & 3;
    int sub = lane >> 3, j8 = lane & 7;

    uint32_t aBase = sb + (uint32_t)((warpM * 64 + j8 + (sub & 1) * 8) * PHB + (sub >> 1) * 16);
    uint32_t bBase = sb + (uint32_t)(TILE_B + (warpN * 32 + j8 + (sub >> 1) * 8) * PHB + (sub & 1) * 16);

    float c[4][4][4];
#pragma unroll
    for (int ma = 0; ma < 4; ma++)
#pragma unroll
        for (int nb = 0; nb < 4; nb++)
#pragma unroll
            for (int r = 0; r < 4; r++) c[ma][nb][r] = 0.f;

    // ---- mainloop 1: A @ W1^T ----
#pragma unroll
    for (int ks = 0; ks < 8; ks++) {
        uint32_t kofs = ks * 32;
        uint32_t af[4][4];
#pragma unroll
        for (int ma = 0; ma < 4; ma++)
            ldsm4(af[ma], aBase + ma * 16 * PHB + kofs);
        uint32_t bf01[4], bf23[4];
        ldsm4(bf01, bBase + kofs);
        ldsm4(bf23, bBase + 16 * PHB + kofs);
#pragma unroll
        for (int ma = 0; ma < 4; ma++) {
            mma_f16(c[ma][0], af[ma], &bf01[0]);
            mma_f16(c[ma][1], af[ma], &bf01[2]);
            mma_f16(c[ma][2], af[ma], &bf23[0]);
            mma_f16(c[ma][3], af[ma], &bf23[2]);
        }
    }
    __syncthreads();   // all reads of A/W1 done

    // prefetch W2 into the (dead) W1 slot
#pragma unroll
    for (int i = 0; i < 8; i++) {
        int o = i * 256 + tid;
        int row = o >> 4;
        int q = o & 15;
        cp16(sb + (uint32_t)(TILE_B + row * PHB + q * 16), W2t + (size_t)row * FD + q * 8);
    }
    asm volatile("cp.async.commit_group;" ::: "memory");

    // T = fp16(relu(acc + b1)) into the (dead) A slot
#pragma unroll
    for (int ma = 0; ma < 4; ma++) {
        int r0 = warpM * 64 + ma * 16 + g;
#pragma unroll
        for (int nb = 0; nb < 4; nb++) {
            int cn = warpN * 32 + nb * 8 + 2 * t;
            float b0 = b1p[cn], b1v = b1p[cn + 1];
            *(__half2*)(smem + r0 * PH + cn) =
                __floats2half2_rn(fmaxf(c[ma][nb][0] + b0, 0.f), fmaxf(c[ma][nb][1] + b1v, 0.f));
            *(__half2*)(smem + (r0 + 8) * PH + cn) =
                __floats2half2_rn(fmaxf(c[ma][nb][2] + b0, 0.f), fmaxf(c[ma][nb][3] + b1v, 0.f));
#pragma unroll
            for (int r = 0; r < 4; r++) c[ma][nb][r] = 0.f;
        }
    }
    asm volatile("cp.async.wait_group 0;" ::: "memory");
    __syncthreads();

    // ---- mainloop 2: T @ W2^T ----
#pragma unroll
    for (int ks = 0; ks < 8; ks++) {
        uint32_t kofs = ks * 32;
        uint32_t af[4][4];
#pragma unroll
        for (int ma = 0; ma < 4; ma++)
            ldsm4(af[ma], aBase + ma * 16 * PHB + kofs);
        uint32_t bf01[4], bf23[4];
        ldsm4(bf01, bBase + kofs);
        ldsm4(bf23, bBase + 16 * PHB + kofs);
#pragma unroll
        for (int ma = 0; ma < 4; ma++) {
            mma_f16(c[ma][0], af[ma], &bf01[0]);
            mma_f16(c[ma][1], af[ma], &bf01[2]);
            mma_f16(c[ma][2], af[ma], &bf23[0]);
            mma_f16(c[ma][3], af[ma], &bf23[2]);
        }
    }

    // epilogue: hb16 = fp16(acc + b2)
#pragma unroll
    for (int ma = 0; ma < 4; ma++) {
        int r0 = m0 + warpM * 64 + ma * 16 + g;
#pragma unroll
        for (int nb = 0; nb < 4; nb++) {
            int cn = warpN * 32 + nb * 8 + 2 * t;
            float b0 = b2p[cn], b1v = b2p[cn + 1];
            if (r0 < M)
                *(__half2*)&C16[(size_t)r0 * FD + cn] =
                    __floats2half2_rn(c[ma][nb][0] + b0, c[ma][nb][1] + b1v);
            if (r0 + 8 < M)
                *(__half2*)&C16[(size_t)(r0 + 8) * FD + cn] =
                    __floats2half2_rn(c[ma][nb][2] + b0, c[ma][nb][3] + b1v);
        }
    }
}

// ---------------- proj GEMM (fp16, LDSM) fused with pool partial-sums ----------------
__global__ void __launch_bounds__(256) k_gemm_proj16(
    const __half* __restrict__ A16, const __half* __restrict__ Wt16,
    const float* __restrict__ bias,
    const int* __restrict__ batch, float* __restrict__ poolp, int M)
{
    extern __shared__ __half smem[];
    uint32_t sb = smem_u32(smem);
    float* Tt = (float*)smem;
    int* sbatch = (int*)((char*)smem + GEMM_SMEM);
    int tid = threadIdx.x;
    int w = tid >> 5, lane = tid & 31;
    int m0 = blockIdx.x * 128;

#pragma unroll
    for (int i = 0; i < 16; i++) {
        int o = i * 256 + tid;
        int side = o >> 11;
        int idx = o & 2047;
        int row = idx >> 4;
        int q = idx & 15;
        uint32_t dst = sb + (uint32_t)(side * TILE_B + row * PHB + q * 16);
        if (side == 0) {
            int m = m0 + row;
            cp16(dst, A16 + ((m < M) ? ((size_t)m * FD + q * 8) : (size_t)(q * 8)));
        } else {
            cp16(dst, Wt16 + (size_t)row * FD + q * 8);
        }
    }
    asm volatile("cp.async.commit_group;" ::: "memory");
    asm volatile("cp.async.wait_group 0;" ::: "memory");
    __syncthreads();

    int warpM = w >> 2, warpN = w & 3;
    int g = lane >> 2, t = lane & 3;
    int sub = lane >> 3, j8 = lane & 7;

    uint32_t aBase = sb + (uint32_t)((warpM * 64 + j8 + (sub & 1) * 8) * PHB + (sub >> 1) * 16);
    uint32_t bBase = sb + (uint32_t)(TILE_B + (warpN * 32 + j8 + (sub >> 1) * 8) * PHB + (sub & 1) * 16);

    float c[4][4][4];
#pragma unroll
    for (int ma = 0; ma < 4; ma++)
#pragma unroll
        for (int nb = 0; nb < 4; nb++)
#pragma unroll
            for (int r = 0; r < 4; r++) c[ma][nb][r] = 0.f;

#pragma unroll
    for (int ks = 0; ks < 8; ks++) {
        uint32_t kofs = ks * 32;
        uint32_t af[4][4];
#pragma unroll
        for (int ma = 0; ma < 4; ma++)
            ldsm4(af[ma], aBase + ma * 16 * PHB + kofs);
        uint32_t bf01[4], bf23[4];
        ldsm4(bf01, bBase + kofs);
        ldsm4(bf23, bBase + 16 * PHB + kofs);
#pragma unroll
        for (int ma = 0; ma < 4; ma++) {
            mma_f16(c[ma][0], af[ma], &bf01[0]);
            mma_f16(c[ma][1], af[ma], &bf01[2]);
            mma_f16(c[ma][2], af[ma], &bf23[0]);
            mma_f16(c[ma][3], af[ma], &bf23[2]);
        }
    }
    __syncthreads();   // operands dead; reuse SMEM for T tile

    if (tid < 128) sbatch[tid] = (m0 + tid < M) ? batch[m0 + tid] : -1;
#pragma unroll
    for (int ma = 0; ma < 4; ma++) {
        int r0 = warpM * 64 + ma * 16 + g;
#pragma unroll
        for (int nb = 0; nb < 4; nb++) {
            int cn = warpN * 32 + nb * 8 + 2 * t;
            float b0 = bias[cn], b1v = bias[cn + 1];
            Tt[r0 * TPIT + cn]           = fmaxf(c[ma][nb][0] + b0, 0.f);
            Tt[r0 * TPIT + cn + 1]       = fmaxf(c[ma][nb][1] + b1v, 0.f);
            Tt[(r0 + 8) * TPIT + cn]     = fmaxf(c[ma][nb][2] + b0, 0.f);
            Tt[(r0 + 8) * TPIT + cn + 1] = fmaxf(c[ma][nb][3] + b1v, 0.f);
        }
    }
    __syncthreads();

    {
        int f = tid & 127;
        int half = tid >> 7;
        int base = half * 64;
        if (m0 + base < M) {
            float acc = 0.f;
            int curg = sbatch[base];
            for (int i = 0; i < 64; i++) {
                int gi = sbatch[base + i];
                if (gi < 0) break;
                if (gi != curg) {
                    atomicAdd(&poolp[(size_t)curg * FD + f], acc);
                    acc = 0.f;
                    curg = gi;
                }
                acc += Tt[(base + i) * TPIT + f];
            }
            if (curg >= 0) atomicAdd(&poolp[(size_t)curg * FD + f], acc);
        }
    }
}

// ---------------- GraphNorm (+relu): fp16 in, fp16 out ----------------
__global__ void __launch_bounds__(128) k_gnorm(
    const __half* __restrict__ hb,
    const float* __restrict__ scale, const float* __restrict__ weight,
    const float* __restrict__ bias)
{
    int g = blockIdx.x;
    int f = threadIdx.x;
    int s = g_gstart[g], e = g_gstart[g + 1];
    float cnt = fmaxf((float)(e - s), 1.0f);

    float sum = 0.f, sq = 0.f;
#pragma unroll 4
    for (int i = s; i < e; i++) {
        float v = __half2float(hb[(size_t)i * FD + f]);
        sum += v;
        sq += v * v;
    }
    float mean = sum / cnt;
    float ms = mean * scale[f];
    float var = sq / cnt - 2.f * ms * mean + ms * ms;
    float inv = weight[f] * rsqrtf(var + 1e-8f);
    float bf = bias[f];

#pragma unroll 4
    for (int i = s; i < e; i++) {
        float v = __half2float(hb[(size_t)i * FD + f]);
        float o = fmaxf(inv * (v - ms) + bf, 0.f);
        g_h16[(size_t)i * FD + f] = __float2half(o);
    }
}

// ---------------- final tiny GEMM ----------------
__global__ void __launch_bounds__(128) k_pool2(
    const float* __restrict__ poolp,
    const float* __restrict__ w2, const float* __restrict__ b2,
    float* __restrict__ out, int lofs)
{
    __shared__ float sp[128];
    int g = blockIdx.x;
    int f = threadIdx.x;
    sp[f] = poolp[(size_t)g * FD + f];
    __syncthreads();
    if (f < TG) {
        int cnt = g_gstart[g + 1] - g_gstart[g];
        float o = (float)cnt * b2[f];
#pragma unroll 8
        for (int k = 0; k < FD; k++) o += sp[k] * w2[k * TG + f];
        out[(size_t)g * (LL * TG) + lofs + f] = o;
    }
}

// ---------------- launcher: two-stream DAG overlap ----------------
extern "C" void kernel_launch(void* const* d_in, const int* in_sizes, int n_in,
                              void* d_out, int out_size) {
    const float* x        = (const float*)d_in[0];
    const int*   edge     = (const int*)d_in[1];
    const int*   batch    = (const int*)d_in[2];
    const float* conv_w1  = (const float*)d_in[3];
    const float* conv_b1  = (const float*)d_in[4];
    const float* conv_w2  = (const float*)d_in[5];
    const float* conv_b2  = (const float*)d_in[6];
    const float* eps      = (const float*)d_in[7];
    const float* gn_scale = (const float*)d_in[8];
    const float* gn_weight= (const float*)d_in[9];
    const float* gn_bias  = (const float*)d_in[10];
    const float* proj_w1  = (const float*)d_in[11];
    const float* proj_b1  = (const float*)d_in[12];
    const float* proj_w2  = (const float*)d_in[13];
    const float* proj_b2  = (const float*)d_in[14];
    float* out = (float*)d_out;

    const int* src = edge;
    const int* dst = edge + EE;

    float* p_pool;
    __half *p_hb16, *p_h16, *p_a16, *p_wt16;
    cudaGetSymbolAddress((void**)&p_pool, g_pool);
    cudaGetSymbolAddress((void**)&p_hb16, g_hb16);
    cudaGetSymbolAddress((void**)&p_h16, g_h16);
    cudaGetSymbolAddress((void**)&p_a16, g_aggr16);
    cudaGetSymbolAddress((void**)&p_wt16, g_wt16);

    cudaFuncSetAttribute(k_gin16, cudaFuncAttributeMaxDynamicSharedMemorySize, GEMM_SMEM);
    cudaFuncSetAttribute(k_gemm_proj16, cudaFuncAttributeMaxDynamicSharedMemorySize, PROJ_SMEM);

    cudaStream_t s2;
    cudaStreamCreateWithFlags(&s2, cudaStreamNonBlocking);
    cudaEvent_t evStart, evPre, evG[LL], evPd[LL], evP[LL];
    cudaEventCreateWithFlags(&evStart, cudaEventDisableTiming);
    cudaEventCreateWithFlags(&evPre, cudaEventDisableTiming);
    for (int l = 0; l < LL; l++) {
        cudaEventCreateWithFlags(&evG[l], cudaEventDisableTiming);
        cudaEventCreateWithFlags(&evPd[l], cudaEventDisableTiming);
        cudaEventCreateWithFlags(&evP[l], cudaEventDisableTiming);
    }

    // fork: wtrans + x16 + gstart on s2, CSR build on main stream
    cudaEventRecord(evStart, 0);
    cudaStreamWaitEvent(s2, evStart, 0);
    k_wtrans<<<dim3(4, 4, 9), dim3(32, 8), 0, s2>>>(conv_w1, conv_w2, proj_w1);
    k_x16<<<(NN * FD / 2 + 255) / 256, 256, 0, s2>>>(x);
    k_gstart<<<3, 256, 0, s2>>>(batch);
    cudaEventRecord(evPre, s2);

    k_init_zero<<<(LL * GG * FD + 255) / 256, 256>>>();
    k_hist<<<(EE + 255) / 256, 256>>>(dst);
    k_scan1<<<NB, 1024>>>();
    k_scan2<<<1, 128>>>();
    k_scan3<<<NB, 1024>>>();
    k_bucket<<<(EE + 255) / 256, 256>>>(src, dst);

    cudaStreamWaitEvent(0, evPre, 0);   // need h16 + wt16 + gstart before layer work

    for (int l = 0; l < LL; l++) {
        // main stream: aggr -> fused MLP -> gnorm
        k_aggr16<<<(NN + 7) / 8, 256>>>(eps + l);
        k_gin16<<<MTILES, 256, GEMM_SMEM>>>(p_a16,
                                            p_wt16 + (size_t)l * FD * FD,
                                            conv_b1 + (size_t)l * FD,
                                            p_wt16 + (size_t)(3 + l) * FD * FD,
                                            conv_b2 + (size_t)l * FD, p_hb16, NN);
        // WAR: gnorm(l) overwrites g_h16, which proj(l-1) reads on s2
        if (l > 0) cudaStreamWaitEvent(0, evPd[l - 1], 0);
        k_gnorm<<<GG, 128>>>(p_hb16, gn_scale + (size_t)l * FD,
                             gn_weight + (size_t)l * FD, gn_bias + (size_t)l * FD);
        cudaEventRecord(evG[l], 0);

        // side stream: proj(l) + pool2(l), overlapped with next layer
        cudaStreamWaitEvent(s2, evG[l], 0);
        k_gemm_proj16<<<MTILES, 256, PROJ_SMEM, s2>>>(p_h16,
                                                      p_wt16 + (size_t)(6 + l) * FD * FD,
                                                      proj_b1 + (size_t)l * FD,
                                                      batch, p_pool + (size_t)l * GG * FD, NN);
        cudaEventRecord(evPd[l], s2);
        k_pool2<<<GG, 128, 0, s2>>>(p_pool + (size_t)l * GG * FD,
                                    proj_w2 + (size_t)l * FD * TG,
                                    proj_b2 + (size_t)l * TG, out, l * TG);
        cudaEventRecord(evP[l], s2);
    }

    for (int l = 0; l < LL; l++)
        cudaStreamWaitEvent(0, evP[l], 0);

    cudaEventDestroy(evStart);
    cudaEventDestroy(evPre);
    for (int l = 0; l < LL; l++) {
        cudaEventDestroy(evG[l]);
        cudaEventDestroy(evPd[l]);
        cudaEventDestroy(evP[l]);
    }
    cudaStreamDestroy(s2);
}

// round 15
// speedup vs baseline: 1.2912x; 1.0778x over previous
#include <cuda_runtime.h>
#include <cuda_fp16.h>
#include <cstdint>

#define NN 100000
#define EE 1600000
#define FD 128
#define GG 512
#define LL 3
#define TG 64
#define NB ((NN + 1023) / 1024)   /* 98 scan blocks */
#define MTILES ((NN + 127) / 128) /* 782 */

#define PH 136                     /* halves per SMEM row; conflict-free for LDSM */
#define PHB (PH * 2)               /* 272 bytes per row */
#define TILE_B (128 * PHB)         /* 34816 B per operand tile */
#define GEMM_SMEM (2 * TILE_B)     /* 69632 B */
#define TPIT 132                   /* fp32 pitch for proj T tile */
#define PROJ_SMEM (GEMM_SMEM + 512)

// ---------------- device scratch (no allocs allowed) ----------------
__device__ __half g_hb16[(size_t)NN * FD];    // fp16 conv2 output (gnorm input)
__device__ __half g_h16[(size_t)NN * FD];     // fp16 activations (gather/proj source)
__device__ __half g_aggr16[(size_t)NN * FD];
__device__ __half g_wt16[9 * FD * FD];        // pre-transposed weights [n][k], fp16
__device__ float  g_pool[LL * GG * FD];
__device__ int    g_deg[NN];
__device__ int    g_rowptr[NN + 1];
__device__ int    g_cursor[NN];
__device__ int    g_bsum[NB];
__device__ int    g_srcsorted[EE];
__device__ int    g_gstart[GG + 1];

__device__ __forceinline__ uint32_t smem_u32(const void* p) {
    uint32_t a;
    asm("{ .reg .u64 t; cvta.to.shared.u64 t, %1; cvt.u32.u64 %0, t; }" : "=r"(a) : "l"(p));
    return a;
}
__device__ __forceinline__ void cp16(uint32_t dst, const void* src) {
    asm volatile("cp.async.cg.shared.global [%0], [%1], 16;"
                 :: "r"(dst), "l"(src) : "memory");
}
__device__ __forceinline__ void mma_f16(float* c, const uint32_t* a, const uint32_t* b) {
    asm volatile(
        "mma.sync.aligned.m16n8k16.row.col.f32.f16.f16.f32 "
        "{%0,%1,%2,%3}, {%4,%5,%6,%7}, {%8,%9}, {%0,%1,%2,%3};"
        : "+f"(c[0]), "+f"(c[1]), "+f"(c[2]), "+f"(c[3])
        : "r"(a[0]), "r"(a[1]), "r"(a[2]), "r"(a[3]), "r"(b[0]), "r"(b[1]));
}
__device__ __forceinline__ void ldsm4(uint32_t* r, uint32_t addr) {
    asm volatile("ldmatrix.sync.aligned.m8n8.x4.shared.b16 {%0,%1,%2,%3}, [%4];"
                 : "=r"(r[0]), "=r"(r[1]), "=r"(r[2]), "=r"(r[3]) : "r"(addr));
}
__device__ __forceinline__ void acc_h4(float4& acc, uint2 v) {
    float2 f0 = __half22float2(*(const __half2*)&v.x);
    float2 f1 = __half22float2(*(const __half2*)&v.y);
    acc.x += f0.x; acc.y += f0.y; acc.z += f1.x; acc.w += f1.y;
}

// ---------------- init / CSR build ----------------
__global__ void k_zero_deg() {
    int i = blockIdx.x * 256 + threadIdx.x;
    if (i < NN) g_deg[i] = 0;
}
__global__ void k_zero_pool() {
    int i = blockIdx.x * 256 + threadIdx.x;
    if (i < LL * GG * FD) g_pool[i] = 0.f;
}
__global__ void k_hist(const int* __restrict__ dst) {
    int e = blockIdx.x * 256 + threadIdx.x;
    if (e < EE) atomicAdd(&g_deg[dst[e]], 1);
}
__global__ void k_scan1() {
    __shared__ int sh[1024];
    int i = blockIdx.x * 1024 + threadIdx.x;
    int v = (i < NN) ? g_deg[i] : 0;
    sh[threadIdx.x] = v;
    __syncthreads();
    for (int off = 1; off < 1024; off <<= 1) {
        int t = sh[threadIdx.x];
        int a = (threadIdx.x >= off) ? sh[threadIdx.x - off] : 0;
        __syncthreads();
        sh[threadIdx.x] = t + a;
        __syncthreads();
    }
    if (i < NN) g_rowptr[i + 1] = sh[threadIdx.x];
    if (threadIdx.x == 1023) g_bsum[blockIdx.x] = sh[1023];
}
// scan3 also performs the 98-entry block-offset scan per block (absorbs old scan2)
__global__ void k_scan3() {
    __shared__ int sh[128];
    int t = threadIdx.x;
    if (t < 128) sh[t] = (t < NB) ? g_bsum[t] : 0;
    __syncthreads();
    for (int off = 1; off < 128; off <<= 1) {
        int x = (t < 128) ? sh[t] : 0;
        int a = (t >= off && t < 128) ? sh[t - off] : 0;
        __syncthreads();
        if (t < 128) sh[t] = x + a;
        __syncthreads();
    }
    int boff = (blockIdx.x == 0) ? 0 : sh[blockIdx.x - 1];   // exclusive block offset
    int i = blockIdx.x * 1024 + t;
    if (i < NN) {
        int v = g_rowptr[i + 1] + boff;
        g_rowptr[i + 1] = v;
        if (i + 1 < NN) g_cursor[i + 1] = v;
    }
    if (i == 0) { g_rowptr[0] = 0; g_cursor[0] = 0; }
}
__global__ void k_bucket(const int* __restrict__ src, const int* __restrict__ dst) {
    int e = blockIdx.x * 256 + threadIdx.x;
    if (e < EE) {
        int d = dst[e];
        int pos = atomicAdd(&g_cursor[d], 1);
        g_srcsorted[pos] = src[e];
    }
}
__global__ void k_gstart(const int* __restrict__ batch) {
    int g = blockIdx.x * 256 + threadIdx.x;
    if (g <= GG) {
        int lo = 0, hi = NN;
        while (lo < hi) {
            int mid = (lo + hi) >> 1;
            if (batch[mid] < g) lo = mid + 1; else hi = mid;
        }
        g_gstart[g] = lo;
    }
}

// ---------------- x -> fp16 ----------------
__global__ void k_x16(const float* __restrict__ x) {
    int i = blockIdx.x * 256 + threadIdx.x;
    if (i < NN * FD / 2) {
        float2 v = ((const float2*)x)[i];
        ((__half2*)g_h16)[i] = __floats2half2_rn(v.x, v.y);
    }
}

// ---------------- weight transpose -> fp16 [n][k] ----------------
__global__ void k_wtrans(const float* __restrict__ w1, const float* __restrict__ w2,
                         const float* __restrict__ w3) {
    __shared__ float t[32][33];
    int mi = blockIdx.z;
    const float* src = (mi < 3) ? (w1 + (size_t)mi * FD * FD)
                     : (mi < 6) ? (w2 + (size_t)(mi - 3) * FD * FD)
                                : (w3 + (size_t)(mi - 6) * FD * FD);
    __half* dst = g_wt16 + (size_t)mi * FD * FD;
    int x0 = blockIdx.x * 32, y0 = blockIdx.y * 32;
    for (int dy = threadIdx.y; dy < 32; dy += 8)
        t[dy][threadIdx.x] = src[(size_t)(y0 + dy) * FD + x0 + threadIdx.x];
    __syncthreads();
    for (int dy = threadIdx.y; dy < 32; dy += 8)
        dst[(size_t)(x0 + dy) * FD + y0 + threadIdx.x] = __float2half(t[threadIdx.x][dy]);
}

// ---------------- aggregation + GIN combine (fp16 in, fp16 out) ----------------
__global__ void __launch_bounds__(256) k_aggr16(const float* __restrict__ epsp) {
    int node = blockIdx.x * 8 + (threadIdx.x >> 5);
    if (node >= NN) return;
    int lane = threadIdx.x & 31;
    int s = g_rowptr[node], e = g_rowptr[node + 1];
    float alpha = 1.0f + epsp[0];
    const uint2* hp = (const uint2*)g_h16;
    uint2 hv = hp[(size_t)node * 32 + lane];
    float2 f0 = __half22float2(*(const __half2*)&hv.x);
    float2 f1 = __half22float2(*(const __half2*)&hv.y);
    float4 acc = make_float4(alpha * f0.x, alpha * f0.y, alpha * f1.x, alpha * f1.y);
    int j = s;
    for (; j + 3 < e; j += 4) {
        int s0 = g_srcsorted[j],     s1 = g_srcsorted[j + 1];
        int s2 = g_srcsorted[j + 2], s3 = g_srcsorted[j + 3];
        uint2 v0 = hp[(size_t)s0 * 32 + lane];
        uint2 v1 = hp[(size_t)s1 * 32 + lane];
        uint2 v2 = hp[(size_t)s2 * 32 + lane];
        uint2 v3 = hp[(size_t)s3 * 32 + lane];
        acc_h4(acc, v0); acc_h4(acc, v1); acc_h4(acc, v2); acc_h4(acc, v3);
    }
    for (; j < e; j++) acc_h4(acc, hp[(size_t)g_srcsorted[j] * 32 + lane]);
    uint2 o;
    *(__half2*)&o.x = __floats2half2_rn(acc.x, acc.y);
    *(__half2*)&o.y = __floats2half2_rn(acc.z, acc.w);
    ((uint2*)g_aggr16)[(size_t)node * 32 + lane] = o;
}

// ---------------- fused GIN MLP: hb16 = fp16(relu(A@W1^T + b1)@W2^T + b2) ----------------
__global__ void __launch_bounds__(256) k_gin16(
    const __half* __restrict__ A16,
    const __half* __restrict__ W1t, const float* __restrict__ b1p,
    const __half* __restrict__ W2t, const float* __restrict__ b2p,
    __half* __restrict__ C16, int M)
{
    extern __shared__ __half smem[];
    uint32_t sb = smem_u32(smem);
    int tid = threadIdx.x;
    int w = tid >> 5, lane = tid & 31;
    int m0 = blockIdx.x * 128;

#pragma unroll
    for (int i = 0; i < 16; i++) {
        int o = i * 256 + tid;
        int side = o >> 11;
        int idx = o & 2047;
        int row = idx >> 4;
        int q = idx & 15;
        uint32_t dst = sb + (uint32_t)(side * TILE_B + row * PHB + q * 16);
        if (side == 0) {
            int m = m0 + row;
            cp16(dst, A16 + ((m < M) ? ((size_t)m * FD + q * 8) : (size_t)(q * 8)));
        } else {
            cp16(dst, W1t + (size_t)row * FD + q * 8);
        }
    }
    asm volatile("cp.async.commit_group;" ::: "memory");
    asm volatile("cp.async.wait_group 0;" ::: "memory");
    __syncthreads();

    int warpM = w >> 2, warpN = w & 3;
    int g = lane >> 2, t = lane & 3;
    int sub = lane >> 3, j8 = lane & 7;

    uint32_t aBase = sb + (uint32_t)((warpM * 64 + j8 + (sub & 1) * 8) * PHB + (sub >> 1) * 16);
    uint32_t bBase = sb + (uint32_t)(TILE_B + (warpN * 32 + j8 + (sub >> 1) * 8) * PHB + (sub & 1) * 16);

    float c[4][4][4];
#pragma unroll
    for (int ma = 0; ma < 4; ma++)
#pragma unroll
        for (int nb = 0; nb < 4; nb++)
#pragma unroll
            for (int r = 0; r < 4; r++) c[ma][nb][r] = 0.f;

    // ---- mainloop 1: A @ W1^T ----
#pragma unroll
    for (int ks = 0; ks < 8; ks++) {
        uint32_t kofs = ks * 32;
        uint32_t af[4][4];
#pragma unroll
        for (int ma = 0; ma < 4; ma++)
            ldsm4(af[ma], aBase + ma * 16 * PHB + kofs);
        uint32_t bf01[4], bf23[4];
        ldsm4(bf01, bBase + kofs);
        ldsm4(bf23, bBase + 16 * PHB + kofs);
#pragma unroll
        for (int ma = 0; ma < 4; ma++) {
            mma_f16(c[ma][0], af[ma], &bf01[0]);
            mma_f16(c[ma][1], af[ma], &bf01[2]);
            mma_f16(c[ma][2], af[ma], &bf23[0]);
            mma_f16(c[ma][3], af[ma], &bf23[2]);
        }
    }
    __syncthreads();

    // prefetch W2 into the (dead) W1 slot
#pragma unroll
    for (int i = 0; i < 8; i++) {
        int o = i * 256 + tid;
        int row = o >> 4;
        int q = o & 15;
        cp16(sb + (uint32_t)(TILE_B + row * PHB + q * 16), W2t + (size_t)row * FD + q * 8);
    }
    asm volatile("cp.async.commit_group;" ::: "memory");

    // T = fp16(relu(acc + b1)) into the (dead) A slot
#pragma unroll
    for (int ma = 0; ma < 4; ma++) {
        int r0 = warpM * 64 + ma * 16 + g;
#pragma unroll
        for (int nb = 0; nb < 4; nb++) {
            int cn = warpN * 32 + nb * 8 + 2 * t;
            float b0 = b1p[cn], b1v = b1p[cn + 1];
            *(__half2*)(smem + r0 * PH + cn) =
                __floats2half2_rn(fmaxf(c[ma][nb][0] + b0, 0.f), fmaxf(c[ma][nb][1] + b1v, 0.f));
            *(__half2*)(smem + (r0 + 8) * PH + cn) =
                __floats2half2_rn(fmaxf(c[ma][nb][2] + b0, 0.f), fmaxf(c[ma][nb][3] + b1v, 0.f));
#pragma unroll
            for (int r = 0; r < 4; r++) c[ma][nb][r] = 0.f;
        }
    }
    asm volatile("cp.async.wait_group 0;" ::: "memory");
    __syncthreads();

    // ---- mainloop 2: T @ W2^T ----
#pragma unroll
    for (int ks = 0; ks < 8; ks++) {
        uint32_t kofs = ks * 32;
        uint32_t af[4][4];
#pragma unroll
        for (int ma = 0; ma < 4; ma++)
            ldsm4(af[ma], aBase + ma * 16 * PHB + kofs);
        uint32_t bf01[4], bf23[4];
        ldsm4(bf01, bBase + kofs);
        ldsm4(bf23, bBase + 16 * PHB + kofs);
#pragma unroll
        for (int ma = 0; ma < 4; ma++) {
            mma_f16(c[ma][0], af[ma], &bf01[0]);
            mma_f16(c[ma][1], af[ma], &bf01[2]);
            mma_f16(c[ma][2], af[ma], &bf23[0]);
            mma_f16(c[ma][3], af[ma], &bf23[2]);
        }
    }

    // epilogue: hb16 = fp16(acc + b2)
#pragma unroll
    for (int ma = 0; ma < 4; ma++) {
        int r0 = m0 + warpM * 64 + ma * 16 + g;
#pragma unroll
        for (int nb = 0; nb < 4; nb++) {
            int cn = warpN * 32 + nb * 8 + 2 * t;
            float b0 = b2p[cn], b1v = b2p[cn + 1];
            if (r0 < M)
                *(__half2*)&C16[(size_t)r0 * FD + cn] =
                    __floats2half2_rn(c[ma][nb][0] + b0, c[ma][nb][1] + b1v);
            if (r0 + 8 < M)
                *(__half2*)&C16[(size_t)(r0 + 8) * FD + cn] =
                    __floats2half2_rn(c[ma][nb][2] + b0, c[ma][nb][3] + b1v);
        }
    }
}

// ---------------- proj GEMM (fp16, LDSM) fused with pool partial-sums ----------------
__global__ void __launch_bounds__(256) k_gemm_proj16(
    const __half* __restrict__ A16, const __half* __restrict__ Wt16,
    const float* __restrict__ bias,
    const int* __restrict__ batch, float* __restrict__ poolp, int M)
{
    extern __shared__ __half smem[];
    uint32_t sb = smem_u32(smem);
    float* Tt = (float*)smem;
    int* sbatch = (int*)((char*)smem + GEMM_SMEM);
    int tid = threadIdx.x;
    int w = tid >> 5, lane = tid & 31;
    int m0 = blockIdx.x * 128;

#pragma unroll
    for (int i = 0; i < 16; i++) {
        int o = i * 256 + tid;
        int side = o >> 11;
        int idx = o & 2047;
        int row = idx >> 4;
        int q = idx & 15;
        uint32_t dst = sb + (uint32_t)(side * TILE_B + row * PHB + q * 16);
        if (side == 0) {
            int m = m0 + row;
            cp16(dst, A16 + ((m < M) ? ((size_t)m * FD + q * 8) : (size_t)(q * 8)));
        } else {
            cp16(dst, Wt16 + (size_t)row * FD + q * 8);
        }
    }
    asm volatile("cp.async.commit_group;" ::: "memory");
    asm volatile("cp.async.wait_group 0;" ::: "memory");
    __syncthreads();

    int warpM = w >> 2, warpN = w & 3;
    int g = lane >> 2, t = lane & 3;
    int sub = lane >> 3, j8 = lane & 7;

    uint32_t aBase = sb + (uint32_t)((warpM * 64 + j8 + (sub & 1) * 8) * PHB + (sub >> 1) * 16);
    uint32_t bBase = sb + (uint32_t)(TILE_B + (warpN * 32 + j8 + (sub >> 1) * 8) * PHB + (sub & 1) * 16);

    float c[4][4][4];
#pragma unroll
    for (int ma = 0; ma < 4; ma++)
#pragma unroll
        for (int nb = 0; nb < 4; nb++)
#pragma unroll
            for (int r = 0; r < 4; r++) c[ma][nb][r] = 0.f;

#pragma unroll
    for (int ks = 0; ks < 8; ks++) {
        uint32_t kofs = ks * 32;
        uint32_t af[4][4];
#pragma unroll
        for (int ma = 0; ma < 4; ma++)
            ldsm4(af[ma], aBase + ma * 16 * PHB + kofs);
        uint32_t bf01[4], bf23[4];
        ldsm4(bf01, bBase + kofs);
        ldsm4(bf23, bBase + 16 * PHB + kofs);
#pragma unroll
        for (int ma = 0; ma < 4; ma++) {
            mma_f16(c[ma][0], af[ma], &bf01[0]);
            mma_f16(c[ma][1], af[ma], &bf01[2]);
            mma_f16(c[ma][2], af[ma], &bf23[0]);
            mma_f16(c[ma][3], af[ma], &bf23[2]);
        }
    }
    __syncthreads();   // operands dead; reuse SMEM for T tile

    if (tid < 128) sbatch[tid] = (m0 + tid < M) ? batch[m0 + tid] : -1;
#pragma unroll
    for (int ma = 0; ma < 4; ma++) {
        int r0 = warpM * 64 + ma * 16 + g;
#pragma unroll
        for (int nb = 0; nb < 4; nb++) {
            int cn = warpN * 32 + nb * 8 + 2 * t;
            float b0 = bias[cn], b1v = bias[cn + 1];
            Tt[r0 * TPIT + cn]           = fmaxf(c[ma][nb][0] + b0, 0.f);
            Tt[r0 * TPIT + cn + 1]       = fmaxf(c[ma][nb][1] + b1v, 0.f);
            Tt[(r0 + 8) * TPIT + cn]     = fmaxf(c[ma][nb][2] + b0, 0.f);
            Tt[(r0 + 8) * TPIT + cn + 1] = fmaxf(c[ma][nb][3] + b1v, 0.f);
        }
    }
    __syncthreads();

    {
        int f = tid & 127;
        int half = tid >> 7;
        int base = half * 64;
        if (m0 + base < M) {
            float acc = 0.f;
            int curg = sbatch[base];
            for (int i = 0; i < 64; i++) {
                int gi = sbatch[base + i];
                if (gi < 0) break;
                if (gi != curg) {
                    atomicAdd(&poolp[(size_t)curg * FD + f], acc);
                    acc = 0.f;
                    curg = gi;
                }
                acc += Tt[(base + i) * TPIT + f];
            }
            if (curg >= 0) atomicAdd(&poolp[(size_t)curg * FD + f], acc);
        }
    }
}

// ---------------- GraphNorm (+relu), 256 threads: rows split across two halves ----------------
__global__ void __launch_bounds__(256) k_gnorm(
    const __half* __restrict__ hb,
    const float* __restrict__ scale, const float* __restrict__ weight,
    const float* __restrict__ bias)
{
    __shared__ float ssum[256], ssq[256];
    int g = blockIdx.x;
    int f = threadIdx.x & 127;
    int half = threadIdx.x >> 7;
    int s = g_gstart[g], e = g_gstart[g + 1];
    int n = e - s;
    int mid = s + (n >> 1);
    int rs = half ? mid : s;
    int re = half ? e : mid;

    float sum = 0.f, sq = 0.f;
#pragma unroll 4
    for (int i = rs; i < re; i++) {
        float v = __half2float(hb[(size_t)i * FD + f]);
        sum += v;
        sq += v * v;
    }
    ssum[threadIdx.x] = sum;
    ssq[threadIdx.x] = sq;
    __syncthreads();
    float tsum = ssum[f] + ssum[f + 128];
    float tsq  = ssq[f] + ssq[f + 128];

    float cnt = fmaxf((float)n, 1.0f);
    float mean = tsum / cnt;
    float ms = mean * scale[f];
    float var = tsq / cnt - 2.f * ms * mean + ms * ms;
    float inv = weight[f] * rsqrtf(var + 1e-8f);
    float bf = bias[f];

#pragma unroll 4
    for (int i = rs; i < re; i++) {
        float v = __half2float(hb[(size_t)i * FD + f]);
        float o = fmaxf(inv * (v - ms) + bf, 0.f);
        g_h16[(size_t)i * FD + f] = __float2half(o);
    }
}

// ---------------- final tiny GEMM ----------------
__global__ void __launch_bounds__(128) k_pool2(
    const float* __restrict__ poolp,
    const float* __restrict__ w2, const float* __restrict__ b2,
    float* __restrict__ out, int lofs)
{
    __shared__ float sp[128];
    int g = blockIdx.x;
    int f = threadIdx.x;
    sp[f] = poolp[(size_t)g * FD + f];
    __syncthreads();
    if (f < TG) {
        int cnt = g_gstart[g + 1] - g_gstart[g];
        float o = (float)cnt * b2[f];
#pragma unroll 8
        for (int k = 0; k < FD; k++) o += sp[k] * w2[k * TG + f];
        out[(size_t)g * (LL * TG) + lofs + f] = o;
    }
}

// ---------------- launcher: two-stream DAG overlap ----------------
extern "C" void kernel_launch(void* const* d_in, const int* in_sizes, int n_in,
                              void* d_out, int out_size) {
    const float* x        = (const float*)d_in[0];
    const int*   edge     = (const int*)d_in[1];
    const int*   batch    = (const int*)d_in[2];
    const float* conv_w1  = (const float*)d_in[3];
    const float* conv_b1  = (const float*)d_in[4];
    const float* conv_w2  = (const float*)d_in[5];
    const float* conv_b2  = (const float*)d_in[6];
    const float* eps      = (const float*)d_in[7];
    const float* gn_scale = (const float*)d_in[8];
    const float* gn_weight= (const float*)d_in[9];
    const float* gn_bias  = (const float*)d_in[10];
    const float* proj_w1  = (const float*)d_in[11];
    const float* proj_b1  = (const float*)d_in[12];
    const float* proj_w2  = (const float*)d_in[13];
    const float* proj_b2  = (const float*)d_in[14];
    float* out = (float*)d_out;

    const int* src = edge;
    const int* dst = edge + EE;

    float* p_pool;
    __half *p_hb16, *p_h16, *p_a16, *p_wt16;
    cudaGetSymbolAddress((void**)&p_pool, g_pool);
    cudaGetSymbolAddress((void**)&p_hb16, g_hb16);
    cudaGetSymbolAddress((void**)&p_h16, g_h16);
    cudaGetSymbolAddress((void**)&p_a16, g_aggr16);
    cudaGetSymbolAddress((void**)&p_wt16, g_wt16);

    cudaFuncSetAttribute(k_gin16, cudaFuncAttributeMaxDynamicSharedMemorySize, GEMM_SMEM);
    cudaFuncSetAttribute(k_gemm_proj16, cudaFuncAttributeMaxDynamicSharedMemorySize, PROJ_SMEM);

    cudaStream_t s2;
    cudaStreamCreateWithFlags(&s2, cudaStreamNonBlocking);
    cudaEvent_t evStart, evPre, evG[LL], evPd[LL], evP[LL];
    cudaEventCreateWithFlags(&evStart, cudaEventDisableTiming);
    cudaEventCreateWithFlags(&evPre, cudaEventDisableTiming);
    for (int l = 0; l < LL; l++) {
        cudaEventCreateWithFlags(&evG[l], cudaEventDisableTiming);
        cudaEventCreateWithFlags(&evPd[l], cudaEventDisableTiming);
        cudaEventCreateWithFlags(&evP[l], cudaEventDisableTiming);
    }

    // fork: wtrans + x16 + gstart + pool-zero on s2, CSR build on main stream
    cudaEventRecord(evStart, 0);
    cudaStreamWaitEvent(s2, evStart, 0);
    k_wtrans<<<dim3(4, 4, 9), dim3(32, 8), 0, s2>>>(conv_w1, conv_w2, proj_w1);
    k_x16<<<(NN * FD / 2 + 255) / 256, 256, 0, s2>>>(x);
    k_gstart<<<3, 256, 0, s2>>>(batch);
    k_zero_pool<<<(LL * GG * FD + 255) / 256, 256, 0, s2>>>();
    cudaEventRecord(evPre, s2);

    k_zero_deg<<<(NN + 255) / 256, 256>>>();
    k_hist<<<(EE + 255) / 256, 256>>>(dst);
    k_scan1<<<NB, 1024>>>();
    k_scan3<<<NB, 1024>>>();
    k_bucket<<<(EE + 255) / 256, 256>>>(src, dst);

    cudaStreamWaitEvent(0, evPre, 0);   // need h16 + wt16 + gstart before layer work

    for (int l = 0; l < LL; l++) {
        // main stream: aggr -> fused MLP -> gnorm
        k_aggr16<<<(NN + 7) / 8, 256>>>(eps + l);
        k_gin16<<<MTILES, 256, GEMM_SMEM>>>(p_a16,
                                            p_wt16 + (size_t)l * FD * FD,
                                            conv_b1 + (size_t)l * FD,
                                            p_wt16 + (size_t)(3 + l) * FD * FD,
                                            conv_b2 + (size_t)l * FD, p_hb16, NN);
        // WAR: gnorm(l) overwrites g_h16, which proj(l-1) reads on s2
        if (l > 0) cudaStreamWaitEvent(0, evPd[l - 1], 0);
        k_gnorm<<<GG, 256>>>(p_hb16, gn_scale + (size_t)l * FD,
                             gn_weight + (size_t)l * FD, gn_bias + (size_t)l * FD);
        cudaEventRecord(evG[l], 0);

        // side stream: proj(l) + pool2(l), overlapped with next layer
        cudaStreamWaitEvent(s2, evG[l], 0);
        k_gemm_proj16<<<MTILES, 256, PROJ_SMEM, s2>>>(p_h16,
                                                      p_wt16 + (size_t)(6 + l) * FD * FD,
                                                      proj_b1 + (size_t)l * FD,
                                                      batch, p_pool + (size_t)l * GG * FD, NN);
        cudaEventRecord(evPd[l], s2);
        k_pool2<<<GG, 128, 0, s2>>>(p_pool + (size_t)l * GG * FD,
                                    proj_w2 + (size_t)l * FD * TG,
                                    proj_b2 + (size_t)l * TG, out, l * TG);
        cudaEventRecord(evP[l], s2);
    }

    for (int l = 0; l < LL; l++)
        cudaStreamWaitEvent(0, evP[l], 0);

    cudaEventDestroy(evStart);
    cudaEventDestroy(evPre);
    for (int l = 0; l < LL; l++) {
        cudaEventDestroy(evG[l]);
        cudaEventDestroy(evPd[l]);
        cudaEventDestroy(evP[l]);
    }
    cudaStreamDestroy(s2);
}

// round 16
// speedup vs baseline: 1.3334x; 1.0327x over previous
#include <cuda_runtime.h>
#include <cuda_fp16.h>
#include <cstdint>

#define NN 100000
#define EE 1600000
#define FD 128
#define GG 512
#define LL 3
#define TG 64
#define NB ((NN + 1023) / 1024)   /* 98 scan blocks */
#define MTILES ((NN + 127) / 128) /* 782 */

#define PH 136                     /* halves per SMEM row; conflict-free for LDSM */
#define PHB (PH * 2)               /* 272 bytes per row */
#define TILE_B (128 * PHB)         /* 34816 B per operand tile */
#define GEMM_SMEM (2 * TILE_B)     /* 69632 B */
#define TPIT 132                   /* fp32 pitch for proj T tile */
#define PROJ_SMEM (GEMM_SMEM + 512)

// ---------------- device scratch (no allocs allowed) ----------------
__device__ __half g_hb16[(size_t)NN * FD];    // fp16 conv2 output (gnorm input)
__device__ __half g_h16[(size_t)NN * FD];     // fp16 activations (gather/proj source)
__device__ __half g_aggr16[(size_t)NN * FD];
__device__ __half g_wt16[9 * FD * FD];        // pre-transposed weights [n][k], fp16
__device__ float  g_pool[LL * GG * FD];
__device__ int    g_deg[NN];
__device__ int    g_rowptr[NN + 1];
__device__ int    g_cursor[NN];
__device__ int    g_bsum[NB];
__device__ int    g_srcsorted[EE];
__device__ int    g_gstart[GG + 1];

__device__ __forceinline__ uint32_t smem_u32(const void* p) {
    uint32_t a;
    asm("{ .reg .u64 t; cvta.to.shared.u64 t, %1; cvt.u32.u64 %0, t; }" : "=r"(a) : "l"(p));
    return a;
}
__device__ __forceinline__ void cp16(uint32_t dst, const void* src) {
    asm volatile("cp.async.cg.shared.global [%0], [%1], 16;"
                 :: "r"(dst), "l"(src) : "memory");
}
__device__ __forceinline__ void mma_f16(float* c, const uint32_t* a, const uint32_t* b) {
    asm volatile(
        "mma.sync.aligned.m16n8k16.row.col.f32.f16.f16.f32 "
        "{%0,%1,%2,%3}, {%4,%5,%6,%7}, {%8,%9}, {%0,%1,%2,%3};"
        : "+f"(c[0]), "+f"(c[1]), "+f"(c[2]), "+f"(c[3])
        : "r"(a[0]), "r"(a[1]), "r"(a[2]), "r"(a[3]), "r"(b[0]), "r"(b[1]));
}
__device__ __forceinline__ void ldsm4(uint32_t* r, uint32_t addr) {
    asm volatile("ldmatrix.sync.aligned.m8n8.x4.shared.b16 {%0,%1,%2,%3}, [%4];"
                 : "=r"(r[0]), "=r"(r[1]), "=r"(r[2]), "=r"(r[3]) : "r"(addr));
}
__device__ __forceinline__ void acc_h8(float4& a0, float4& a1, uint4 v) {
    float2 f0 = __half22float2(*(const __half2*)&v.x);
    float2 f1 = __half22float2(*(const __half2*)&v.y);
    float2 f2 = __half22float2(*(const __half2*)&v.z);
    float2 f3 = __half22float2(*(const __half2*)&v.w);
    a0.x += f0.x; a0.y += f0.y; a0.z += f1.x; a0.w += f1.y;
    a1.x += f2.x; a1.y += f2.y; a1.z += f3.x; a1.w += f3.y;
}

// ---------------- CSR build ----------------
__global__ void k_hist(const int* __restrict__ dst) {
    int e = blockIdx.x * 256 + threadIdx.x;
    if (e < EE) atomicAdd(&g_deg[dst[e]], 1);
}
__global__ void k_scan1() {
    __shared__ int sh[1024];
    int i = blockIdx.x * 1024 + threadIdx.x;
    int v = (i < NN) ? g_deg[i] : 0;
    sh[threadIdx.x] = v;
    __syncthreads();
    for (int off = 1; off < 1024; off <<= 1) {
        int t = sh[threadIdx.x];
        int a = (threadIdx.x >= off) ? sh[threadIdx.x - off] : 0;
        __syncthreads();
        sh[threadIdx.x] = t + a;
        __syncthreads();
    }
    if (i < NN) g_rowptr[i + 1] = sh[threadIdx.x];
    if (threadIdx.x == 1023) g_bsum[blockIdx.x] = sh[1023];
}
// scan3 also performs the 98-entry block-offset scan per block (absorbs old scan2)
__global__ void k_scan3() {
    __shared__ int sh[128];
    int t = threadIdx.x;
    if (t < 128) sh[t] = (t < NB) ? g_bsum[t] : 0;
    __syncthreads();
    for (int off = 1; off < 128; off <<= 1) {
        int x = (t < 128) ? sh[t] : 0;
        int a = (t >= off && t < 128) ? sh[t - off] : 0;
        __syncthreads();
        if (t < 128) sh[t] = x + a;
        __syncthreads();
    }
    int boff = (blockIdx.x == 0) ? 0 : sh[blockIdx.x - 1];   // exclusive block offset
    int i = blockIdx.x * 1024 + t;
    if (i < NN) {
        int v = g_rowptr[i + 1] + boff;
        g_rowptr[i + 1] = v;
        if (i + 1 < NN) g_cursor[i + 1] = v;
    }
    if (i == 0) { g_rowptr[0] = 0; g_cursor[0] = 0; }
}
__global__ void k_bucket(const int* __restrict__ src, const int* __restrict__ dst) {
    int e = blockIdx.x * 256 + threadIdx.x;
    if (e < EE) {
        int d = dst[e];
        int pos = atomicAdd(&g_cursor[d], 1);
        g_srcsorted[pos] = src[e];
    }
}
__global__ void k_gstart(const int* __restrict__ batch) {
    int g = blockIdx.x * 256 + threadIdx.x;
    if (g <= GG) {
        int lo = 0, hi = NN;
        while (lo < hi) {
            int mid = (lo + hi) >> 1;
            if (batch[mid] < g) lo = mid + 1; else hi = mid;
        }
        g_gstart[g] = lo;
    }
}

// ---------------- x -> fp16 ----------------
__global__ void k_x16(const float* __restrict__ x) {
    int i = blockIdx.x * 256 + threadIdx.x;
    if (i < NN * FD / 2) {
        float2 v = ((const float2*)x)[i];
        ((__half2*)g_h16)[i] = __floats2half2_rn(v.x, v.y);
    }
}

// ---------------- weight transpose -> fp16 [n][k] ----------------
__global__ void k_wtrans(const float* __restrict__ w1, const float* __restrict__ w2,
                         const float* __restrict__ w3) {
    __shared__ float t[32][33];
    int mi = blockIdx.z;
    const float* src = (mi < 3) ? (w1 + (size_t)mi * FD * FD)
                     : (mi < 6) ? (w2 + (size_t)(mi - 3) * FD * FD)
                                : (w3 + (size_t)(mi - 6) * FD * FD);
    __half* dst = g_wt16 + (size_t)mi * FD * FD;
    int x0 = blockIdx.x * 32, y0 = blockIdx.y * 32;
    for (int dy = threadIdx.y; dy < 32; dy += 8)
        t[dy][threadIdx.x] = src[(size_t)(y0 + dy) * FD + x0 + threadIdx.x];
    __syncthreads();
    for (int dy = threadIdx.y; dy < 32; dy += 8)
        dst[(size_t)(x0 + dy) * FD + y0 + threadIdx.x] = __float2half(t[threadIdx.x][dy]);
}

// ---------------- aggregation + GIN combine: 2 nodes/warp, uint4 gathers ----------------
__global__ void __launch_bounds__(256) k_aggr16(const float* __restrict__ epsp) {
    int warp = blockIdx.x * 8 + (threadIdx.x >> 5);
    int lane = threadIdx.x & 31;
    int node = warp * 2 + (lane >> 4);        // lanes 0-15: node A, 16-31: node B
    if (node >= NN) return;
    int l16 = lane & 15;                      // uint4 slot within 256B row
    int s = g_rowptr[node], e = g_rowptr[node + 1];
    float alpha = 1.0f + epsp[0];
    const uint4* hp = (const uint4*)g_h16;    // 8 halves per lane slot
    uint4 hv = hp[(size_t)node * 16 + l16];
    float4 a0 = make_float4(0.f, 0.f, 0.f, 0.f), a1 = a0;
    acc_h8(a0, a1, hv);
    a0.x *= alpha; a0.y *= alpha; a0.z *= alpha; a0.w *= alpha;
    a1.x *= alpha; a1.y *= alpha; a1.z *= alpha; a1.w *= alpha;
    int j = s;
    for (; j + 3 < e; j += 4) {
        int s0 = g_srcsorted[j],     s1 = g_srcsorted[j + 1];
        int s2 = g_srcsorted[j + 2], s3 = g_srcsorted[j + 3];
        uint4 v0 = hp[(size_t)s0 * 16 + l16];
        uint4 v1 = hp[(size_t)s1 * 16 + l16];
        uint4 v2 = hp[(size_t)s2 * 16 + l16];
        uint4 v3 = hp[(size_t)s3 * 16 + l16];
        acc_h8(a0, a1, v0); acc_h8(a0, a1, v1);
        acc_h8(a0, a1, v2); acc_h8(a0, a1, v3);
    }
    for (; j < e; j++) acc_h8(a0, a1, hp[(size_t)g_srcsorted[j] * 16 + l16]);
    uint4 o;
    *(__half2*)&o.x = __floats2half2_rn(a0.x, a0.y);
    *(__half2*)&o.y = __floats2half2_rn(a0.z, a0.w);
    *(__half2*)&o.z = __floats2half2_rn(a1.x, a1.y);
    *(__half2*)&o.w = __floats2half2_rn(a1.z, a1.w);
    ((uint4*)g_aggr16)[(size_t)node * 16 + l16] = o;
}

// ---------------- fused GIN MLP: hb16 = fp16(relu(A@W1^T + b1)@W2^T + b2) ----------------
__global__ void __launch_bounds__(256) k_gin16(
    const __half* __restrict__ A16,
    const __half* __restrict__ W1t, const float* __restrict__ b1p,
    const __half* __restrict__ W2t, const float* __restrict__ b2p,
    __half* __restrict__ C16, int M)
{
    extern __shared__ __half smem[];
    uint32_t sb = smem_u32(smem);
    int tid = threadIdx.x;
    int w = tid >> 5, lane = tid & 31;
    int m0 = blockIdx.x * 128;

#pragma unroll
    for (int i = 0; i < 16; i++) {
        int o = i * 256 + tid;
        int side = o >> 11;
        int idx = o & 2047;
        int row = idx >> 4;
        int q = idx & 15;
        uint32_t dst = sb + (uint32_t)(side * TILE_B + row * PHB + q * 16);
        if (side == 0) {
            int m = m0 + row;
            cp16(dst, A16 + ((m < M) ? ((size_t)m * FD + q * 8) : (size_t)(q * 8)));
        } else {
            cp16(dst, W1t + (size_t)row * FD + q * 8);
        }
    }
    asm volatile("cp.async.commit_group;" ::: "memory");
    asm volatile("cp.async.wait_group 0;" ::: "memory");
    __syncthreads();

    int warpM = w >> 2, warpN = w & 3;
    int g = lane >> 2, t = lane & 3;
    int sub = lane >> 3, j8 = lane & 7;

    uint32_t aBase = sb + (uint32_t)((warpM * 64 + j8 + (sub & 1) * 8) * PHB + (sub >> 1) * 16);
    uint32_t bBase = sb + (uint32_t)(TILE_B + (warpN * 32 + j8 + (sub >> 1) * 8) * PHB + (sub & 1) * 16);

    float c[4][4][4];
#pragma unroll
    for (int ma = 0; ma < 4; ma++)
#pragma unroll
        for (int nb = 0; nb < 4; nb++)
#pragma unroll
            for (int r = 0; r < 4; r++) c[ma][nb][r] = 0.f;

    // ---- mainloop 1: A @ W1^T ----
#pragma unroll
    for (int ks = 0; ks < 8; ks++) {
        uint32_t kofs = ks * 32;
        uint32_t af[4][4];
#pragma unroll
        for (int ma = 0; ma < 4; ma++)
            ldsm4(af[ma], aBase + ma * 16 * PHB + kofs);
        uint32_t bf01[4], bf23[4];
        ldsm4(bf01, bBase + kofs);
        ldsm4(bf23, bBase + 16 * PHB + kofs);
#pragma unroll
        for (int ma = 0; ma < 4; ma++) {
            mma_f16(c[ma][0], af[ma], &bf01[0]);
            mma_f16(c[ma][1], af[ma], &bf01[2]);
            mma_f16(c[ma][2], af[ma], &bf23[0]);
            mma_f16(c[ma][3], af[ma], &bf23[2]);
        }
    }
    __syncthreads();

    // prefetch W2 into the (dead) W1 slot
#pragma unroll
    for (int i = 0; i < 8; i++) {
        int o = i * 256 + tid;
        int row = o >> 4;
        int q = o & 15;
        cp16(sb + (uint32_t)(TILE_B + row * PHB + q * 16), W2t + (size_t)row * FD + q * 8);
    }
    asm volatile("cp.async.commit_group;" ::: "memory");

    // T = fp16(relu(acc + b1)) into the (dead) A slot
#pragma unroll
    for (int ma = 0; ma < 4; ma++) {
        int r0 = warpM * 64 + ma * 16 + g;
#pragma unroll
        for (int nb = 0; nb < 4; nb++) {
            int cn = warpN * 32 + nb * 8 + 2 * t;
            float b0 = b1p[cn], b1v = b1p[cn + 1];
            *(__half2*)(smem + r0 * PH + cn) =
                __floats2half2_rn(fmaxf(c[ma][nb][0] + b0, 0.f), fmaxf(c[ma][nb][1] + b1v, 0.f));
            *(__half2*)(smem + (r0 + 8) * PH + cn) =
                __floats2half2_rn(fmaxf(c[ma][nb][2] + b0, 0.f), fmaxf(c[ma][nb][3] + b1v, 0.f));
#pragma unroll
            for (int r = 0; r < 4; r++) c[ma][nb][r] = 0.f;
        }
    }
    asm volatile("cp.async.wait_group 0;" ::: "memory");
    __syncthreads();

    // ---- mainloop 2: T @ W2^T ----
#pragma unroll
    for (int ks = 0; ks < 8; ks++) {
        uint32_t kofs = ks * 32;
        uint32_t af[4][4];
#pragma unroll
        for (int ma = 0; ma < 4; ma++)
            ldsm4(af[ma], aBase + ma * 16 * PHB + kofs);
        uint32_t bf01[4], bf23[4];
        ldsm4(bf01, bBase + kofs);
        ldsm4(bf23, bBase + 16 * PHB + kofs);
#pragma unroll
        for (int ma = 0; ma < 4; ma++) {
            mma_f16(c[ma][0], af[ma], &bf01[0]);
            mma_f16(c[ma][1], af[ma], &bf01[2]);
            mma_f16(c[ma][2], af[ma], &bf23[0]);
            mma_f16(c[ma][3], af[ma], &bf23[2]);
        }
    }

    // epilogue: hb16 = fp16(acc + b2)
#pragma unroll
    for (int ma = 0; ma < 4; ma++) {
        int r0 = m0 + warpM * 64 + ma * 16 + g;
#pragma unroll
        for (int nb = 0; nb < 4; nb++) {
            int cn = warpN * 32 + nb * 8 + 2 * t;
            float b0 = b2p[cn], b1v = b2p[cn + 1];
            if (r0 < M)
                *(__half2*)&C16[(size_t)r0 * FD + cn] =
                    __floats2half2_rn(c[ma][nb][0] + b0, c[ma][nb][1] + b1v);
            if (r0 + 8 < M)
                *(__half2*)&C16[(size_t)(r0 + 8) * FD + cn] =
                    __floats2half2_rn(c[ma][nb][2] + b0, c[ma][nb][3] + b1v);
        }
    }
}

// ---------------- proj GEMM (fp16, LDSM) fused with pool partial-sums ----------------
__global__ void __launch_bounds__(256) k_gemm_proj16(
    const __half* __restrict__ A16, const __half* __restrict__ Wt16,
    const float* __restrict__ bias,
    const int* __restrict__ batch, float* __restrict__ poolp, int M)
{
    extern __shared__ __half smem[];
    uint32_t sb = smem_u32(smem);
    float* Tt = (float*)smem;
    int* sbatch = (int*)((char*)smem + GEMM_SMEM);
    int tid = threadIdx.x;
    int w = tid >> 5, lane = tid & 31;
    int m0 = blockIdx.x * 128;

#pragma unroll
    for (int i = 0; i < 16; i++) {
        int o = i * 256 + tid;
        int side = o >> 11;
        int idx = o & 2047;
        int row = idx >> 4;
        int q = idx & 15;
        uint32_t dst = sb + (uint32_t)(side * TILE_B + row * PHB + q * 16);
        if (side == 0) {
            int m = m0 + row;
            cp16(dst, A16 + ((m < M) ? ((size_t)m * FD + q * 8) : (size_t)(q * 8)));
        } else {
            cp16(dst, Wt16 + (size_t)row * FD + q * 8);
        }
    }
    asm volatile("cp.async.commit_group;" ::: "memory");
    asm volatile("cp.async.wait_group 0;" ::: "memory");
    __syncthreads();

    int warpM = w >> 2, warpN = w & 3;
    int g = lane >> 2, t = lane & 3;
    int sub = lane >> 3, j8 = lane & 7;

    uint32_t aBase = sb + (uint32_t)((warpM * 64 + j8 + (sub & 1) * 8) * PHB + (sub >> 1) * 16);
    uint32_t bBase = sb + (uint32_t)(TILE_B + (warpN * 32 + j8 + (sub >> 1) * 8) * PHB + (sub & 1) * 16);

    float c[4][4][4];
#pragma unroll
    for (int ma = 0; ma < 4; ma++)
#pragma unroll
        for (int nb = 0; nb < 4; nb++)
#pragma unroll
            for (int r = 0; r < 4; r++) c[ma][nb][r] = 0.f;

#pragma unroll
    for (int ks = 0; ks < 8; ks++) {
        uint32_t kofs = ks * 32;
        uint32_t af[4][4];
#pragma unroll
        for (int ma = 0; ma < 4; ma++)
            ldsm4(af[ma], aBase + ma * 16 * PHB + kofs);
        uint32_t bf01[4], bf23[4];
        ldsm4(bf01, bBase + kofs);
        ldsm4(bf23, bBase + 16 * PHB + kofs);
#pragma unroll
        for (int ma = 0; ma < 4; ma++) {
            mma_f16(c[ma][0], af[ma], &bf01[0]);
            mma_f16(c[ma][1], af[ma], &bf01[2]);
            mma_f16(c[ma][2], af[ma], &bf23[0]);
            mma_f16(c[ma][3], af[ma], &bf23[2]);
        }
    }
    __syncthreads();   // operands dead; reuse SMEM for T tile

    if (tid < 128) sbatch[tid] = (m0 + tid < M) ? batch[m0 + tid] : -1;
#pragma unroll
    for (int ma = 0; ma < 4; ma++) {
        int r0 = warpM * 64 + ma * 16 + g;
#pragma unroll
        for (int nb = 0; nb < 4; nb++) {
            int cn = warpN * 32 + nb * 8 + 2 * t;
            float b0 = bias[cn], b1v = bias[cn + 1];
            Tt[r0 * TPIT + cn]           = fmaxf(c[ma][nb][0] + b0, 0.f);
            Tt[r0 * TPIT + cn + 1]       = fmaxf(c[ma][nb][1] + b1v, 0.f);
            Tt[(r0 + 8) * TPIT + cn]     = fmaxf(c[ma][nb][2] + b0, 0.f);
            Tt[(r0 + 8) * TPIT + cn + 1] = fmaxf(c[ma][nb][3] + b1v, 0.f);
        }
    }
    __syncthreads();

    {
        int f = tid & 127;
        int half = tid >> 7;
        int base = half * 64;
        if (m0 + base < M) {
            float acc = 0.f;
            int curg = sbatch[base];
            for (int i = 0; i < 64; i++) {
                int gi = sbatch[base + i];
                if (gi < 0) break;
                if (gi != curg) {
                    atomicAdd(&poolp[(size_t)curg * FD + f], acc);
                    acc = 0.f;
                    curg = gi;
                }
                acc += Tt[(base + i) * TPIT + f];
            }
            if (curg >= 0) atomicAdd(&poolp[(size_t)curg * FD + f], acc);
        }
    }
}

// ---------------- GraphNorm (+relu), 256 threads: rows split across two halves ----------------
__global__ void __launch_bounds__(256) k_gnorm(
    const __half* __restrict__ hb,
    const float* __restrict__ scale, const float* __restrict__ weight,
    const float* __restrict__ bias)
{
    __shared__ float ssum[256], ssq[256];
    int g = blockIdx.x;
    int f = threadIdx.x & 127;
    int half = threadIdx.x >> 7;
    int s = g_gstart[g], e = g_gstart[g + 1];
    int n = e - s;
    int mid = s + (n >> 1);
    int rs = half ? mid : s;
    int re = half ? e : mid;

    float sum = 0.f, sq = 0.f;
#pragma unroll 4
    for (int i = rs; i < re; i++) {
        float v = __half2float(hb[(size_t)i * FD + f]);
        sum += v;
        sq += v * v;
    }
    ssum[threadIdx.x] = sum;
    ssq[threadIdx.x] = sq;
    __syncthreads();
    float tsum = ssum[f] + ssum[f + 128];
    float tsq  = ssq[f] + ssq[f + 128];

    float cnt = fmaxf((float)n, 1.0f);
    float mean = tsum / cnt;
    float ms = mean * scale[f];
    float var = tsq / cnt - 2.f * ms * mean + ms * ms;
    float inv = weight[f] * rsqrtf(var + 1e-8f);
    float bf = bias[f];

#pragma unroll 4
    for (int i = rs; i < re; i++) {
        float v = __half2float(hb[(size_t)i * FD + f]);
        float o = fmaxf(inv * (v - ms) + bf, 0.f);
        g_h16[(size_t)i * FD + f] = __float2half(o);
    }
}

// ---------------- final tiny GEMM ----------------
__global__ void __launch_bounds__(128) k_pool2(
    const float* __restrict__ poolp,
    const float* __restrict__ w2, const float* __restrict__ b2,
    float* __restrict__ out, int lofs)
{
    __shared__ float sp[128];
    int g = blockIdx.x;
    int f = threadIdx.x;
    sp[f] = poolp[(size_t)g * FD + f];
    __syncthreads();
    if (f < TG) {
        int cnt = g_gstart[g + 1] - g_gstart[g];
        float o = (float)cnt * b2[f];
#pragma unroll 8
        for (int k = 0; k < FD; k++) o += sp[k] * w2[k * TG + f];
        out[(size_t)g * (LL * TG) + lofs + f] = o;
    }
}

// ---------------- launcher: two-stream DAG overlap ----------------
extern "C" void kernel_launch(void* const* d_in, const int* in_sizes, int n_in,
                              void* d_out, int out_size) {
    const float* x        = (const float*)d_in[0];
    const int*   edge     = (const int*)d_in[1];
    const int*   batch    = (const int*)d_in[2];
    const float* conv_w1  = (const float*)d_in[3];
    const float* conv_b1  = (const float*)d_in[4];
    const float* conv_w2  = (const float*)d_in[5];
    const float* conv_b2  = (const float*)d_in[6];
    const float* eps      = (const float*)d_in[7];
    const float* gn_scale = (const float*)d_in[8];
    const float* gn_weight= (const float*)d_in[9];
    const float* gn_bias  = (const float*)d_in[10];
    const float* proj_w1  = (const float*)d_in[11];
    const float* proj_b1  = (const float*)d_in[12];
    const float* proj_w2  = (const float*)d_in[13];
    const float* proj_b2  = (const float*)d_in[14];
    float* out = (float*)d_out;

    const int* src = edge;
    const int* dst = edge + EE;

    float* p_pool;
    __half *p_hb16, *p_h16, *p_a16, *p_wt16;
    int *p_deg;
    cudaGetSymbolAddress((void**)&p_pool, g_pool);
    cudaGetSymbolAddress((void**)&p_hb16, g_hb16);
    cudaGetSymbolAddress((void**)&p_h16, g_h16);
    cudaGetSymbolAddress((void**)&p_a16, g_aggr16);
    cudaGetSymbolAddress((void**)&p_wt16, g_wt16);
    cudaGetSymbolAddress((void**)&p_deg, g_deg);

    cudaFuncSetAttribute(k_gin16, cudaFuncAttributeMaxDynamicSharedMemorySize, GEMM_SMEM);
    cudaFuncSetAttribute(k_gemm_proj16, cudaFuncAttributeMaxDynamicSharedMemorySize, PROJ_SMEM);

    cudaStream_t s2;
    cudaStreamCreateWithFlags(&s2, cudaStreamNonBlocking);
    cudaEvent_t evStart, evPre, evG[LL], evPd[LL], evP[LL];
    cudaEventCreateWithFlags(&evStart, cudaEventDisableTiming);
    cudaEventCreateWithFlags(&evPre, cudaEventDisableTiming);
    for (int l = 0; l < LL; l++) {
        cudaEventCreateWithFlags(&evG[l], cudaEventDisableTiming);
        cudaEventCreateWithFlags(&evPd[l], cudaEventDisableTiming);
        cudaEventCreateWithFlags(&evP[l], cudaEventDisableTiming);
    }

    // fork: wtrans + x16 + gstart + pool-zero on s2, CSR build on main stream
    cudaEventRecord(evStart, 0);
    cudaStreamWaitEvent(s2, evStart, 0);
    k_wtrans<<<dim3(4, 4, 9), dim3(32, 8), 0, s2>>>(conv_w1, conv_w2, proj_w1);
    k_x16<<<(NN * FD / 2 + 255) / 256, 256, 0, s2>>>(x);
    k_gstart<<<3, 256, 0, s2>>>(batch);
    cudaMemsetAsync(p_pool, 0, (size_t)LL * GG * FD * sizeof(float), s2);
    cudaEventRecord(evPre, s2);

    cudaMemsetAsync(p_deg, 0, (size_t)NN * sizeof(int), 0);
    k_hist<<<(EE + 255) / 256, 256>>>(dst);
    k_scan1<<<NB, 1024>>>();
    k_scan3<<<NB, 1024>>>();
    k_bucket<<<(EE + 255) / 256, 256>>>(src, dst);

    cudaStreamWaitEvent(0, evPre, 0);   // need h16 + wt16 + gstart before layer work

    for (int l = 0; l < LL; l++) {
        // main stream: aggr -> fused MLP -> gnorm
        k_aggr16<<<(NN / 2 + 7) / 8, 256>>>(eps + l);
        k_gin16<<<MTILES, 256, GEMM_SMEM>>>(p_a16,
                                            p_wt16 + (size_t)l * FD * FD,
                                            conv_b1 + (size_t)l * FD,
                                            p_wt16 + (size_t)(3 + l) * FD * FD,
                                            conv_b2 + (size_t)l * FD, p_hb16, NN);
        // WAR: gnorm(l) overwrites g_h16, which proj(l-1) reads on s2
        if (l > 0) cudaStreamWaitEvent(0, evPd[l - 1], 0);
        k_gnorm<<<GG, 256>>>(p_hb16, gn_scale + (size_t)l * FD,
                             gn_weight + (size_t)l * FD, gn_bias + (size_t)l * FD);
        cudaEventRecord(evG[l], 0);

        if (l < LL - 1) {
            // side stream: proj(l) + pool2(l), overlapped with next layer
            cudaStreamWaitEvent(s2, evG[l], 0);
            k_gemm_proj16<<<MTILES, 256, PROJ_SMEM, s2>>>(p_h16,
                                                          p_wt16 + (size_t)(6 + l) * FD * FD,
                                                          proj_b1 + (size_t)l * FD,
                                                          batch, p_pool + (size_t)l * GG * FD, NN);
            cudaEventRecord(evPd[l], s2);
            k_pool2<<<GG, 128, 0, s2>>>(p_pool + (size_t)l * GG * FD,
                                        proj_w2 + (size_t)l * FD * TG,
                                        proj_b2 + (size_t)l * TG, out, l * TG);
            cudaEventRecord(evP[l], s2);
        } else {
            // last layer: run tail on main stream (nothing left to overlap)
            k_gemm_proj16<<<MTILES, 256, PROJ_SMEM>>>(p_h16,
                                                      p_wt16 + (size_t)(6 + l) * FD * FD,
                                                      proj_b1 + (size_t)l * FD,
                                                      batch, p_pool + (size_t)l * GG * FD, NN);
            k_pool2<<<GG, 128>>>(p_pool + (size_t)l * GG * FD,
                                 proj_w2 + (size_t)l * FD * TG,
                                 proj_b2 + (size_t)l * TG, out, l * TG);
        }
    }

    for (int l = 0; l < LL - 1; l++)
        cudaStreamWaitEvent(0, evP[l], 0);

    cudaEventDestroy(evStart);
    cudaEventDestroy(evPre);
    for (int l = 0; l < LL; l++) {
        cudaEventDestroy(evG[l]);
        cudaEventDestroy(evPd[l]);
        cudaEventDestroy(evP[l]);
    }
    cudaStreamDestroy(s2);
}